// round 1
// baseline (speedup 1.0000x reference)
#include <cuda_runtime.h>
#include <cuda_bf16.h>
#include <math.h>

#define Bsz       16
#define Hh        32
#define Ww        32
#define Nn        1024          // H*W
#define C_SEARCH  256
#define C_XCORR   64
#define Cc        320           // C_SEARCH + C_XCORR
#define PHI_H     64
#define GC_HID    128
#define E_MAX     10068         // 48*47 + 7812
#define BN_EPS    1e-5f

// ---------------- scratch (device globals; no runtime allocation) ----------------
__device__ float g_featT[Bsz * Nn * Cc];                 // [B][N][C]  node-major features
__device__ float g_h[Bsz * E_MAX * PHI_H];               // [B][E][64] phi hidden
__device__ float g_bn_sum[Bsz * PHI_H];
__device__ float g_bn_sumsq[Bsz * PHI_H];
__device__ float g_edgew[Bsz * E_MAX];
__device__ int   g_deg[Bsz * Nn];
__device__ int   g_rowptr[Bsz * (Nn + 1)];
__device__ int   g_cursor[Bsz * Nn];
__device__ int   g_cols[Bsz * E_MAX];
__device__ float g_vals[Bsz * E_MAX];
__device__ float g_X1[Bsz * Nn * GC_HID];                // [B][N][128]
__device__ float g_X2[Bsz * Nn];

// ---------------- K-init: zero accumulators ----------------
__global__ void zero_kernel() {
    int i = blockIdx.x * blockDim.x + threadIdx.x;
    if (i < Bsz * Nn) g_deg[i] = 0;
    if (i < Bsz * PHI_H) { g_bn_sum[i] = 0.f; g_bn_sumsq[i] = 0.f; }
}

// ---------------- K0: build featT [B][N][C] (tiled transpose of concat) ----------------
__global__ void transpose_kernel(const float* __restrict__ search,
                                 const float* __restrict__ xcorr) {
    __shared__ float tile[32][33];
    int b  = blockIdx.z;
    int c0 = blockIdx.y * 32;
    int n0 = blockIdx.x * 32;
    int tx = threadIdx.x, ty = threadIdx.y;
    int c = c0 + ty, n = n0 + tx;
    float v;
    if (c < C_SEARCH)
        v = search[((size_t)b * C_SEARCH + c) * Nn + n];
    else
        v = xcorr[((size_t)b * C_XCORR + (c - C_SEARCH)) * Nn + n];
    tile[ty][tx] = v;
    __syncthreads();
    // write featT[b][n0+ty][c0+tx]
    g_featT[((size_t)b * Nn + n0 + ty) * Cc + c0 + tx] = tile[tx][ty];
}

// ---------------- K1: phi hidden GEMM  h = |f[p0]-f[p1]| @ W1 + b1, + BN partial sums ----
// Tile: 64 edges x 64 outputs, K-chunk 32. 256 threads, 4x4 per-thread register tile.
__global__ __launch_bounds__(256) void phi_gemm_kernel(
        const int* __restrict__ pairs,   // [B][E][2]
        const float* __restrict__ w1,    // [320][64]
        const float* __restrict__ b1,    // [64]
        int E) {
    int b  = blockIdx.y;
    int e0 = blockIdx.x * 64;
    __shared__ int2  sPair[64];
    __shared__ float sA[64][33];
    __shared__ float sW[32][64];
    __shared__ float sSum[64], sSq[64];

    int tid  = threadIdx.x;
    int warp = tid >> 5, lane = tid & 31;
    int ty = tid >> 4, tx = tid & 15;

    if (tid < 64) {
        int e = e0 + tid;
        int2 p = (e < E) ? ((const int2*)pairs)[(size_t)b * E + e] : make_int2(0, 0);
        sPair[tid] = p;
        sSum[tid] = 0.f; sSq[tid] = 0.f;
    }
    float acc[4][4] = {};
    const float* fb = g_featT + (size_t)b * Nn * Cc;

    for (int kc = 0; kc < Cc; kc += 32) {
        __syncthreads();
        // load W chunk: rows kc..kc+31, 2048 contiguous floats
        #pragma unroll
        for (int i = 0; i < 8; i++) {
            int idx = tid + i * 256;
            ((float*)sW)[idx] = w1[kc * 64 + idx];
        }
        // build |diff| tile: each warp 8 edges, lane = k within chunk
        #pragma unroll
        for (int i = 0; i < 8; i++) {
            int er = warp * 8 + i;
            int2 p = sPair[er];
            float v = fabsf(fb[(size_t)p.x * Cc + kc + lane] -
                            fb[(size_t)p.y * Cc + kc + lane]);
            if (e0 + er >= E) v = 0.f;
            sA[er][lane] = v;
        }
        __syncthreads();
        #pragma unroll
        for (int kk = 0; kk < 32; kk++) {
            float a0 = sA[ty * 4 + 0][kk];
            float a1 = sA[ty * 4 + 1][kk];
            float a2 = sA[ty * 4 + 2][kk];
            float a3 = sA[ty * 4 + 3][kk];
            float4 w = *(const float4*)&sW[kk][tx * 4];
            acc[0][0] += a0 * w.x; acc[0][1] += a0 * w.y; acc[0][2] += a0 * w.z; acc[0][3] += a0 * w.w;
            acc[1][0] += a1 * w.x; acc[1][1] += a1 * w.y; acc[1][2] += a1 * w.z; acc[1][3] += a1 * w.w;
            acc[2][0] += a2 * w.x; acc[2][1] += a2 * w.y; acc[2][2] += a2 * w.z; acc[2][3] += a2 * w.w;
            acc[3][0] += a3 * w.x; acc[3][1] += a3 * w.y; acc[3][2] += a3 * w.z; acc[3][3] += a3 * w.w;
        }
    }
    __syncthreads();
    float bias0 = b1[tx * 4 + 0], bias1 = b1[tx * 4 + 1];
    float bias2 = b1[tx * 4 + 2], bias3 = b1[tx * 4 + 3];
    float cs0 = 0, cs1 = 0, cs2 = 0, cs3 = 0;
    float cq0 = 0, cq1 = 0, cq2 = 0, cq3 = 0;
    #pragma unroll
    for (int r = 0; r < 4; r++) {
        int e = e0 + ty * 4 + r;
        if (e < E) {
            float4 hv;
            hv.x = acc[r][0] + bias0;
            hv.y = acc[r][1] + bias1;
            hv.z = acc[r][2] + bias2;
            hv.w = acc[r][3] + bias3;
            *(float4*)&g_h[(((size_t)b * E_MAX) + e) * PHI_H + tx * 4] = hv;
            cs0 += hv.x; cq0 += hv.x * hv.x;
            cs1 += hv.y; cq1 += hv.y * hv.y;
            cs2 += hv.z; cq2 += hv.z * hv.z;
            cs3 += hv.w; cq3 += hv.w * hv.w;
        }
    }
    atomicAdd(&sSum[tx * 4 + 0], cs0); atomicAdd(&sSq[tx * 4 + 0], cq0);
    atomicAdd(&sSum[tx * 4 + 1], cs1); atomicAdd(&sSq[tx * 4 + 1], cq1);
    atomicAdd(&sSum[tx * 4 + 2], cs2); atomicAdd(&sSq[tx * 4 + 2], cq2);
    atomicAdd(&sSum[tx * 4 + 3], cs3); atomicAdd(&sSq[tx * 4 + 3], cq3);
    __syncthreads();
    if (tid < 64) {
        atomicAdd(&g_bn_sum[b * PHI_H + tid], sSum[tid]);
        atomicAdd(&g_bn_sumsq[b * PHI_H + tid], sSq[tid]);
    }
}

// ---------------- K2: BN + ReLU + Linear(64->1) + sigmoid -> edge weights ----------------
__global__ __launch_bounds__(256) void edge_weight_kernel(
        const float* __restrict__ gamma, const float* __restrict__ beta,
        const float* __restrict__ w2, const float* __restrict__ b2, int E) {
    int b = blockIdx.y;
    __shared__ float sa[64], sc[64], sw2[64];
    int tid = threadIdx.x;
    if (tid < 64) {
        float mu  = g_bn_sum[b * PHI_H + tid] / (float)E;
        float var = g_bn_sumsq[b * PHI_H + tid] / (float)E - mu * mu;
        var = fmaxf(var, 0.f);
        float inv = rsqrtf(var + BN_EPS);
        float a = gamma[tid] * inv;
        sa[tid] = a;
        sc[tid] = beta[tid] - mu * a;
        sw2[tid] = w2[tid];
    }
    __syncthreads();
    int warp = tid >> 5, lane = tid & 31;
    int e = blockIdx.x * 8 + warp;
    if (e >= E) return;
    const float* hr = &g_h[(((size_t)b * E_MAX) + e) * PHI_H];
    float v0 = fmaxf(sa[lane]      * hr[lane]      + sc[lane],      0.f);
    float v1 = fmaxf(sa[lane + 32] * hr[lane + 32] + sc[lane + 32], 0.f);
    float p = v0 * sw2[lane] + v1 * sw2[lane + 32];
    #pragma unroll
    for (int o = 16; o; o >>= 1) p += __shfl_xor_sync(0xffffffffu, p, o);
    if (lane == 0) {
        float z = p + b2[0];
        g_edgew[b * E_MAX + e] = 1.f / (1.f + expf(-z));
    }
}

// ---------------- K3a: degree count ----------------
__global__ void count_kernel(const int* __restrict__ pairs, int E) {
    int idx = blockIdx.x * blockDim.x + threadIdx.x;
    if (idx >= Bsz * E) return;
    int b = idx / E, e = idx % E;
    int p0 = pairs[((size_t)b * E + e) * 2];
    atomicAdd(&g_deg[b * Nn + p0], 1);
}

// ---------------- K3b: per-image exclusive scan (N=1024) ----------------
__global__ __launch_bounds__(1024) void scan_kernel(int E) {
    int b = blockIdx.x, tid = threadIdx.x;
    int v = g_deg[b * Nn + tid];
    int x = v;
    #pragma unroll
    for (int o = 1; o < 32; o <<= 1) {
        int y = __shfl_up_sync(0xffffffffu, x, o);
        if ((tid & 31) >= o) x += y;
    }
    __shared__ int wsum[32];
    if ((tid & 31) == 31) wsum[tid >> 5] = x;
    __syncthreads();
    if (tid < 32) {
        int y = wsum[tid];
        #pragma unroll
        for (int o = 1; o < 32; o <<= 1) {
            int z = __shfl_up_sync(0xffffffffu, y, o);
            if (tid >= o) y += z;
        }
        wsum[tid] = y;
    }
    __syncthreads();
    int incl = x + ((tid >= 32) ? wsum[(tid >> 5) - 1] : 0);
    int excl = incl - v;
    g_rowptr[b * (Nn + 1) + tid] = excl;
    g_cursor[b * Nn + tid] = excl;
    if (tid == Nn - 1) g_rowptr[b * (Nn + 1) + Nn] = incl;
}

// ---------------- K3c: scatter into CSR ----------------
__global__ void scatter_kernel(const int* __restrict__ pairs, int E) {
    int idx = blockIdx.x * blockDim.x + threadIdx.x;
    if (idx >= Bsz * E) return;
    int b = idx / E, e = idx % E;
    int p0 = pairs[((size_t)b * E + e) * 2 + 0];
    int p1 = pairs[((size_t)b * E + e) * 2 + 1];
    int pos = atomicAdd(&g_cursor[b * Nn + p0], 1);
    g_cols[b * E_MAX + pos] = p1;
    g_vals[b * E_MAX + pos] = g_edgew[b * E_MAX + e];
}

// ---------------- K4: X1 = featT[16384,320] @ gc1_w[320,128] ----------------
__global__ __launch_bounds__(256) void x1_gemm_kernel(const float* __restrict__ gw) {
    int m0 = blockIdx.x * 64;
    int n0 = blockIdx.y * 64;
    __shared__ float sA[64][33];
    __shared__ float sB[32][64];
    int tid = threadIdx.x;
    int ty = tid >> 4, tx = tid & 15;
    float acc[4][4] = {};
    for (int kc = 0; kc < Cc; kc += 32) {
        __syncthreads();
        // A tile: 64 rows x 32 k
        #pragma unroll
        for (int pass = 0; pass < 2; pass++) {
            int row = (tid >> 3) + pass * 32;
            int kg  = (tid & 7) * 4;
            float4 a4 = *(const float4*)&g_featT[((size_t)(m0 + row)) * Cc + kc + kg];
            sA[row][kg + 0] = a4.x; sA[row][kg + 1] = a4.y;
            sA[row][kg + 2] = a4.z; sA[row][kg + 3] = a4.w;
        }
        // B tile: 32 k x 64 n
        #pragma unroll
        for (int i = 0; i < 8; i++) {
            int idx = tid + i * 256;
            int row = idx >> 6, col = idx & 63;
            sB[row][col] = gw[(kc + row) * GC_HID + n0 + col];
        }
        __syncthreads();
        #pragma unroll
        for (int kk = 0; kk < 32; kk++) {
            float a0 = sA[ty * 4 + 0][kk];
            float a1 = sA[ty * 4 + 1][kk];
            float a2 = sA[ty * 4 + 2][kk];
            float a3 = sA[ty * 4 + 3][kk];
            float4 w = *(const float4*)&sB[kk][tx * 4];
            acc[0][0] += a0 * w.x; acc[0][1] += a0 * w.y; acc[0][2] += a0 * w.z; acc[0][3] += a0 * w.w;
            acc[1][0] += a1 * w.x; acc[1][1] += a1 * w.y; acc[1][2] += a1 * w.z; acc[1][3] += a1 * w.w;
            acc[2][0] += a2 * w.x; acc[2][1] += a2 * w.y; acc[2][2] += a2 * w.z; acc[2][3] += a2 * w.w;
            acc[3][0] += a3 * w.x; acc[3][1] += a3 * w.y; acc[3][2] += a3 * w.z; acc[3][3] += a3 * w.w;
        }
    }
    #pragma unroll
    for (int r = 0; r < 4; r++) {
        float4 o;
        o.x = acc[r][0]; o.y = acc[r][1]; o.z = acc[r][2]; o.w = acc[r][3];
        *(float4*)&g_X1[((size_t)(m0 + ty * 4 + r)) * GC_HID + n0 + tx * 4] = o;
    }
}

// ---------------- K5: SpMM h2 = leaky(A @ X1); fused X2 = h2 @ gc2_w ----------------
__global__ __launch_bounds__(256) void spmm_kernel(const float* __restrict__ gc2, int E) {
    int warp = threadIdx.x >> 5, lane = threadIdx.x & 31;
    int n = blockIdx.x * 8 + warp;
    int b = blockIdx.y;
    int s = g_rowptr[b * (Nn + 1) + n];
    int t = g_rowptr[b * (Nn + 1) + n + 1];
    float a0 = 0, a1 = 0, a2 = 0, a3 = 0;
    const float* Xb = g_X1 + (size_t)b * Nn * GC_HID;
    for (int k = s; k < t; k++) {
        float w = g_vals[b * E_MAX + k];
        int   c = g_cols[b * E_MAX + k];
        const float* xr = Xb + (size_t)c * GC_HID + lane;
        a0 += w * xr[0];
        a1 += w * xr[32];
        a2 += w * xr[64];
        a3 += w * xr[96];
    }
    a0 = (a0 > 0.f) ? a0 : 0.2f * a0;
    a1 = (a1 > 0.f) ? a1 : 0.2f * a1;
    a2 = (a2 > 0.f) ? a2 : 0.2f * a2;
    a3 = (a3 > 0.f) ? a3 : 0.2f * a3;
    float p = a0 * gc2[lane] + a1 * gc2[lane + 32] + a2 * gc2[lane + 64] + a3 * gc2[lane + 96];
    #pragma unroll
    for (int o = 16; o; o >>= 1) p += __shfl_xor_sync(0xffffffffu, p, o);
    if (lane == 0) g_X2[b * Nn + n] = p;
}

// ---------------- K6: out = sigmoid(A @ X2) ----------------
__global__ void finalize_kernel(float* __restrict__ out, int E) {
    int idx = blockIdx.x * blockDim.x + threadIdx.x;
    if (idx >= Bsz * Nn) return;
    int b = idx / Nn, n = idx % Nn;
    int s = g_rowptr[b * (Nn + 1) + n];
    int t = g_rowptr[b * (Nn + 1) + n + 1];
    float acc = 0.f;
    for (int k = s; k < t; k++)
        acc += g_vals[b * E_MAX + k] * g_X2[b * Nn + g_cols[b * E_MAX + k]];
    out[idx] = 1.f / (1.f + expf(-acc));
}

// ---------------- launch ----------------
extern "C" void kernel_launch(void* const* d_in, const int* in_sizes, int n_in,
                              void* d_out, int out_size) {
    const float* search = (const float*)d_in[0];
    const float* xcorr  = (const float*)d_in[1];
    const int*   pairs  = (const int*)d_in[2];
    const float* phi_w1 = (const float*)d_in[3];
    const float* phi_b1 = (const float*)d_in[4];
    const float* gamma  = (const float*)d_in[5];
    const float* beta   = (const float*)d_in[6];
    const float* phi_w2 = (const float*)d_in[7];
    const float* phi_b2 = (const float*)d_in[8];
    const float* gc1_w  = (const float*)d_in[9];
    const float* gc2_w  = (const float*)d_in[10];
    float* out = (float*)d_out;

    int E = in_sizes[2] / (2 * Bsz);
    if (E > E_MAX) E = E_MAX;

    zero_kernel<<<(Bsz * Nn + 255) / 256, 256>>>();
    transpose_kernel<<<dim3(Nn / 32, Cc / 32, Bsz), dim3(32, 32)>>>(search, xcorr);
    phi_gemm_kernel<<<dim3((E + 63) / 64, Bsz), 256>>>(pairs, phi_w1, phi_b1, E);
    edge_weight_kernel<<<dim3((E + 7) / 8, Bsz), 256>>>(gamma, beta, phi_w2, phi_b2, E);
    count_kernel<<<(Bsz * E + 255) / 256, 256>>>(pairs, E);
    scan_kernel<<<Bsz, 1024>>>(E);
    scatter_kernel<<<(Bsz * E + 255) / 256, 256>>>(pairs, E);
    x1_gemm_kernel<<<dim3((Bsz * Nn) / 64, GC_HID / 64), 256>>>(gc1_w);
    spmm_kernel<<<dim3(Nn / 8, Bsz), 256>>>(gc2_w, E);
    finalize_kernel<<<(Bsz * Nn + 255) / 256, 256>>>(out, E);
}

// round 4
// speedup vs baseline: 1.1141x; 1.1141x over previous
#include <cuda_runtime.h>
#include <cuda_bf16.h>
#include <math.h>
#include <cstdint>

#define Bsz       16
#define Nn        1024
#define C_SEARCH  256
#define C_XCORR   64
#define Cc        320
#define PHI_H     64
#define GC_HID    128
#define E_MAX     10068
#define BN_EPS    1e-5f
#define BLK_E     128
#define KCHUNK    16
#define SA_STR    20          // A smem stride: 20 mod 32 pattern -> conflict-free frags
#define SW_STR    72          // W smem stride: 72 mod 32 = 8 -> conflict-free frags

// ---------------- scratch ----------------
__device__ float g_featT[Bsz * Nn * Cc];
__device__ float g_w1hi[Cc * PHI_H];
__device__ float g_w1lo[Cc * PHI_H];
__device__ float g_gwhi[Cc * GC_HID];
__device__ float g_gwlo[Cc * GC_HID];
__device__ float g_h[Bsz * E_MAX * PHI_H];
__device__ float g_bn_sum[Bsz * PHI_H];
__device__ float g_bn_sumsq[Bsz * PHI_H];
__device__ float g_edgew[Bsz * E_MAX];
__device__ int   g_deg[Bsz * Nn];
__device__ int   g_rowptr[Bsz * (Nn + 1)];
__device__ int   g_cursor[Bsz * Nn];
__device__ int   g_cols[Bsz * E_MAX];
__device__ float g_vals[Bsz * E_MAX];
__device__ float g_X1[Bsz * Nn * GC_HID];
__device__ float g_X2[Bsz * Nn];

__device__ __forceinline__ float to_tf32(float x) {
    float y; asm("cvt.rna.tf32.f32 %0, %1;" : "=f"(y) : "f"(x)); return y;
}

__device__ __forceinline__ void mma_tf32(float* d, const uint32_t* a, const uint32_t* b) {
    asm volatile(
        "mma.sync.aligned.m16n8k8.row.col.f32.tf32.tf32.f32 "
        "{%0,%1,%2,%3}, {%4,%5,%6,%7}, {%8,%9}, {%0,%1,%2,%3};"
        : "+f"(d[0]), "+f"(d[1]), "+f"(d[2]), "+f"(d[3])
        : "r"(a[0]), "r"(a[1]), "r"(a[2]), "r"(a[3]), "r"(b[0]), "r"(b[1]));
}

// ---------------- small kernels ----------------
__global__ void zero_kernel() {
    int i = blockIdx.x * blockDim.x + threadIdx.x;
    if (i < Bsz * Nn) g_deg[i] = 0;
    if (i < Bsz * PHI_H) { g_bn_sum[i] = 0.f; g_bn_sumsq[i] = 0.f; }
}

__global__ void wsplit_kernel(const float* __restrict__ w1,
                              const float* __restrict__ gw) {
    int i = blockIdx.x * blockDim.x + threadIdx.x;
    if (i < Cc * PHI_H) {
        float v = w1[i];
        float hi = to_tf32(v);
        g_w1hi[i] = hi;
        g_w1lo[i] = to_tf32(v - hi);
    }
    if (i < Cc * GC_HID) {
        float v = gw[i];
        float hi = to_tf32(v);
        g_gwhi[i] = hi;
        g_gwlo[i] = to_tf32(v - hi);
    }
}

__global__ void transpose_kernel(const float* __restrict__ search,
                                 const float* __restrict__ xcorr) {
    __shared__ float tile[32][33];
    int b  = blockIdx.z;
    int c0 = blockIdx.y * 32;
    int n0 = blockIdx.x * 32;
    int tx = threadIdx.x, ty = threadIdx.y;
    int c = c0 + ty, n = n0 + tx;
    float v;
    if (c < C_SEARCH) v = search[((size_t)b * C_SEARCH + c) * Nn + n];
    else              v = xcorr[((size_t)b * C_XCORR + (c - C_SEARCH)) * Nn + n];
    tile[ty][tx] = v;
    __syncthreads();
    g_featT[((size_t)b * Nn + n0 + ty) * Cc + c0 + tx] = tile[tx][ty];
}

// ---------------- K1: phi GEMM via 3xTF32 mma.sync ----------------
// 128 threads = 4 warps; block tile 128 edges x 64 cols; warp tile 32x64.
__global__ __launch_bounds__(128) void phi_mma_kernel(
        const int* __restrict__ pairs, const float* __restrict__ b1, int E) {
    __shared__ float sAh[BLK_E * SA_STR];
    __shared__ float sAl[BLK_E * SA_STR];
    __shared__ float sWh[KCHUNK * SW_STR];
    __shared__ float sWl[KCHUNK * SW_STR];
    __shared__ float sBias[64], sSum[64], sSq[64];

    int tid = threadIdx.x, warp = tid >> 5, lane = tid & 31;
    int gid = lane >> 2, tig = lane & 3;
    int b = blockIdx.y, e0 = blockIdx.x * BLK_E;

    if (tid < 64) { sBias[tid] = b1[tid]; sSum[tid] = 0.f; sSq[tid] = 0.f; }

    int e = e0 + tid;
    int2 p = (e < E) ? ((const int2*)pairs)[(size_t)b * E + e] : make_int2(0, 0);
    const float* fb   = g_featT + (size_t)b * Nn * Cc;
    const float* rowx = fb + (size_t)p.x * Cc;
    const float* rowy = fb + (size_t)p.y * Cc;

    float acc[2][8][4] = {};

    for (int kc = 0; kc < Cc; kc += KCHUNK) {
        __syncthreads();
        // A tile: one edge row per thread, 16 diffs, split hi/lo
        #pragma unroll
        for (int j = 0; j < 4; j++) {
            float4 xa = *(const float4*)(rowx + kc + j * 4);
            float4 xb = *(const float4*)(rowy + kc + j * 4);
            float4 dh, dl;
            float d;
            d = fabsf(xa.x - xb.x); dh.x = to_tf32(d); dl.x = to_tf32(d - dh.x);
            d = fabsf(xa.y - xb.y); dh.y = to_tf32(d); dl.y = to_tf32(d - dh.y);
            d = fabsf(xa.z - xb.z); dh.z = to_tf32(d); dl.z = to_tf32(d - dh.z);
            d = fabsf(xa.w - xb.w); dh.w = to_tf32(d); dl.w = to_tf32(d - dh.w);
            *(float4*)&sAh[tid * SA_STR + j * 4] = dh;
            *(float4*)&sAl[tid * SA_STR + j * 4] = dl;
        }
        // W tile: 16 k-rows x 64 cols, hi/lo precomputed
        #pragma unroll
        for (int i = 0; i < 2; i++) {
            int idx = tid + i * 128;          // 0..255 float4
            int row = idx >> 4, c4 = idx & 15;
            float4 wh = *(const float4*)(g_w1hi + (size_t)(kc + row) * 64 + c4 * 4);
            float4 wl = *(const float4*)(g_w1lo + (size_t)(kc + row) * 64 + c4 * 4);
            *(float4*)&sWh[row * SW_STR + c4 * 4] = wh;
            *(float4*)&sWl[row * SW_STR + c4 * 4] = wl;
        }
        __syncthreads();

        #pragma unroll
        for (int ks = 0; ks < 2; ks++) {
            int k0 = ks * 8;
            uint32_t bh[8][2], bl[8][2];
            #pragma unroll
            for (int nt = 0; nt < 8; nt++) {
                int c = nt * 8 + gid;
                bh[nt][0] = __float_as_uint(sWh[(k0 + tig)     * SW_STR + c]);
                bh[nt][1] = __float_as_uint(sWh[(k0 + tig + 4) * SW_STR + c]);
                bl[nt][0] = __float_as_uint(sWl[(k0 + tig)     * SW_STR + c]);
                bl[nt][1] = __float_as_uint(sWl[(k0 + tig + 4) * SW_STR + c]);
            }
            #pragma unroll
            for (int mt = 0; mt < 2; mt++) {
                int r = warp * 32 + mt * 16 + gid;
                uint32_t ah[4], al[4];
                ah[0] = __float_as_uint(sAh[r       * SA_STR + k0 + tig]);
                ah[1] = __float_as_uint(sAh[(r + 8) * SA_STR + k0 + tig]);
                ah[2] = __float_as_uint(sAh[r       * SA_STR + k0 + tig + 4]);
                ah[3] = __float_as_uint(sAh[(r + 8) * SA_STR + k0 + tig + 4]);
                al[0] = __float_as_uint(sAl[r       * SA_STR + k0 + tig]);
                al[1] = __float_as_uint(sAl[(r + 8) * SA_STR + k0 + tig]);
                al[2] = __float_as_uint(sAl[r       * SA_STR + k0 + tig + 4]);
                al[3] = __float_as_uint(sAl[(r + 8) * SA_STR + k0 + tig + 4]);
                #pragma unroll
                for (int nt = 0; nt < 8; nt++) {
                    mma_tf32(acc[mt][nt], ah, bh[nt]);
                    mma_tf32(acc[mt][nt], ah, bl[nt]);
                    mma_tf32(acc[mt][nt], al, bh[nt]);
                }
            }
        }
    }
    __syncthreads();

    // epilogue: bias, store h, BN partial sums
    float ts[8][2] = {}, tq[8][2] = {};
    #pragma unroll
    for (int mt = 0; mt < 2; mt++) {
        #pragma unroll
        for (int rh = 0; rh < 2; rh++) {
            int el = warp * 32 + mt * 16 + rh * 8 + gid;
            int e2 = e0 + el;
            bool valid = (e2 < E);
            float* dst = g_h + (((size_t)b * E_MAX) + e2) * PHI_H;
            #pragma unroll
            for (int nt = 0; nt < 8; nt++) {
                int col = nt * 8 + tig * 2;
                float v0 = acc[mt][nt][rh * 2 + 0] + sBias[col];
                float v1 = acc[mt][nt][rh * 2 + 1] + sBias[col + 1];
                if (valid) {
                    *(float2*)(dst + col) = make_float2(v0, v1);
                    ts[nt][0] += v0; tq[nt][0] += v0 * v0;
                    ts[nt][1] += v1; tq[nt][1] += v1 * v1;
                }
            }
        }
    }
    #pragma unroll
    for (int nt = 0; nt < 8; nt++) {
        #pragma unroll
        for (int j = 0; j < 2; j++) {
            float s = ts[nt][j], q = tq[nt][j];
            #pragma unroll
            for (int o = 4; o < 32; o <<= 1) {
                s += __shfl_xor_sync(0xffffffffu, s, o);
                q += __shfl_xor_sync(0xffffffffu, q, o);
            }
            if (gid == 0) {
                int col = nt * 8 + tig * 2 + j;
                atomicAdd(&sSum[col], s);
                atomicAdd(&sSq[col], q);
            }
        }
    }
    __syncthreads();
    if (tid < 64) {
        atomicAdd(&g_bn_sum[b * PHI_H + tid], sSum[tid]);
        atomicAdd(&g_bn_sumsq[b * PHI_H + tid], sSq[tid]);
    }
}

// ---------------- K2: BN + ReLU + Linear + sigmoid (coalesced float4) ----------------
__global__ __launch_bounds__(256) void edge_weight_kernel(
        const float* __restrict__ gamma, const float* __restrict__ beta,
        const float* __restrict__ w2, const float* __restrict__ b2, int E) {
    int b = blockIdx.y;
    __shared__ __align__(16) float sa[64], sc[64], sw2[64];
    int tid = threadIdx.x;
    if (tid < 64) {
        float mu  = g_bn_sum[b * PHI_H + tid] / (float)E;
        float var = g_bn_sumsq[b * PHI_H + tid] / (float)E - mu * mu;
        var = fmaxf(var, 0.f);
        float inv = rsqrtf(var + BN_EPS);
        float a = gamma[tid] * inv;
        sa[tid] = a;
        sc[tid] = beta[tid] - mu * a;
        sw2[tid] = w2[tid];
    }
    __syncthreads();
    int warp = tid >> 5, lane = tid & 31;
    int sub = lane >> 4, l16 = lane & 15;
    float4 A = *(float4*)&sa[l16 * 4];
    float4 C = *(float4*)&sc[l16 * 4];
    float4 W = *(float4*)&sw2[l16 * 4];
    float bb = b2[0];
    int base = blockIdx.x * 256 + warp * 32;
    #pragma unroll 4
    for (int it = 0; it < 16; it++) {
        int e = base + it * 2 + sub;
        if (e >= E) continue;
        float4 h4 = *(const float4*)(g_h + (((size_t)b * E_MAX) + e) * PHI_H + l16 * 4);
        float p = fmaxf(A.x * h4.x + C.x, 0.f) * W.x
                + fmaxf(A.y * h4.y + C.y, 0.f) * W.y
                + fmaxf(A.z * h4.z + C.z, 0.f) * W.z
                + fmaxf(A.w * h4.w + C.w, 0.f) * W.w;
        #pragma unroll
        for (int o = 8; o; o >>= 1) p += __shfl_xor_sync(0xffffffffu, p, o);
        if (l16 == 0) {
            float z = p + bb;
            g_edgew[b * E_MAX + e] = 1.f / (1.f + expf(-z));
        }
    }
}

// ---------------- CSR build ----------------
__global__ void count_kernel(const int* __restrict__ pairs, int E) {
    int idx = blockIdx.x * blockDim.x + threadIdx.x;
    if (idx >= Bsz * E) return;
    int b = idx / E, e = idx % E;
    atomicAdd(&g_deg[b * Nn + pairs[((size_t)b * E + e) * 2]], 1);
}

__global__ __launch_bounds__(1024) void scan_kernel(int E) {
    int b = blockIdx.x, tid = threadIdx.x;
    int v = g_deg[b * Nn + tid];
    int x = v;
    #pragma unroll
    for (int o = 1; o < 32; o <<= 1) {
        int y = __shfl_up_sync(0xffffffffu, x, o);
        if ((tid & 31) >= o) x += y;
    }
    __shared__ int wsum[32];
    if ((tid & 31) == 31) wsum[tid >> 5] = x;
    __syncthreads();
    if (tid < 32) {
        int y = wsum[tid];
        #pragma unroll
        for (int o = 1; o < 32; o <<= 1) {
            int z = __shfl_up_sync(0xffffffffu, y, o);
            if (tid >= o) y += z;
        }
        wsum[tid] = y;
    }
    __syncthreads();
    int incl = x + ((tid >= 32) ? wsum[(tid >> 5) - 1] : 0);
    int excl = incl - v;
    g_rowptr[b * (Nn + 1) + tid] = excl;
    g_cursor[b * Nn + tid] = excl;
    if (tid == Nn - 1) g_rowptr[b * (Nn + 1) + Nn] = incl;
}

__global__ void scatter_kernel(const int* __restrict__ pairs, int E) {
    int idx = blockIdx.x * blockDim.x + threadIdx.x;
    if (idx >= Bsz * E) return;
    int b = idx / E, e = idx % E;
    int p0 = pairs[((size_t)b * E + e) * 2 + 0];
    int p1 = pairs[((size_t)b * E + e) * 2 + 1];
    int pos = atomicAdd(&g_cursor[b * Nn + p0], 1);
    g_cols[b * E_MAX + pos] = p1;
    g_vals[b * E_MAX + pos] = g_edgew[b * E_MAX + e];
}

// ---------------- K4: X1 = featT @ gc1_w via 3xTF32 mma.sync ----------------
__global__ __launch_bounds__(128) void x1_mma_kernel() {
    __shared__ float sAh[128 * SA_STR];
    __shared__ float sAl[128 * SA_STR];
    __shared__ float sWh[KCHUNK * SW_STR];
    __shared__ float sWl[KCHUNK * SW_STR];

    int tid = threadIdx.x, warp = tid >> 5, lane = tid & 31;
    int gid = lane >> 2, tig = lane & 3;
    int m0 = blockIdx.x * 128;
    int n0 = blockIdx.y * 64;

    float acc[2][8][4] = {};

    for (int kc = 0; kc < Cc; kc += KCHUNK) {
        __syncthreads();
        // A tile: 128 rows x 16 k, split hi/lo
        #pragma unroll
        for (int i = 0; i < 4; i++) {
            int idx = tid + i * 128;          // 0..511 float4
            int row = idx >> 2, c4 = idx & 3;
            float4 a = *(const float4*)(g_featT + (size_t)(m0 + row) * Cc + kc + c4 * 4);
            float4 ah4, al4;
            ah4.x = to_tf32(a.x); al4.x = to_tf32(a.x - ah4.x);
            ah4.y = to_tf32(a.y); al4.y = to_tf32(a.y - ah4.y);
            ah4.z = to_tf32(a.z); al4.z = to_tf32(a.z - ah4.z);
            ah4.w = to_tf32(a.w); al4.w = to_tf32(a.w - ah4.w);
            *(float4*)&sAh[row * SA_STR + c4 * 4] = ah4;
            *(float4*)&sAl[row * SA_STR + c4 * 4] = al4;
        }
        // W tile: 16 k-rows x 64 cols from split gc1_w
        #pragma unroll
        for (int i = 0; i < 2; i++) {
            int idx = tid + i * 128;
            int row = idx >> 4, c4 = idx & 15;
            float4 wh = *(const float4*)(g_gwhi + (size_t)(kc + row) * GC_HID + n0 + c4 * 4);
            float4 wl = *(const float4*)(g_gwlo + (size_t)(kc + row) * GC_HID + n0 + c4 * 4);
            *(float4*)&sWh[row * SW_STR + c4 * 4] = wh;
            *(float4*)&sWl[row * SW_STR + c4 * 4] = wl;
        }
        __syncthreads();

        #pragma unroll
        for (int ks = 0; ks < 2; ks++) {
            int k0 = ks * 8;
            uint32_t bh[8][2], bl[8][2];
            #pragma unroll
            for (int nt = 0; nt < 8; nt++) {
                int c = nt * 8 + gid;
                bh[nt][0] = __float_as_uint(sWh[(k0 + tig)     * SW_STR + c]);
                bh[nt][1] = __float_as_uint(sWh[(k0 + tig + 4) * SW_STR + c]);
                bl[nt][0] = __float_as_uint(sWl[(k0 + tig)     * SW_STR + c]);
                bl[nt][1] = __float_as_uint(sWl[(k0 + tig + 4) * SW_STR + c]);
            }
            #pragma unroll
            for (int mt = 0; mt < 2; mt++) {
                int r = warp * 32 + mt * 16 + gid;
                uint32_t ah[4], al[4];
                ah[0] = __float_as_uint(sAh[r       * SA_STR + k0 + tig]);
                ah[1] = __float_as_uint(sAh[(r + 8) * SA_STR + k0 + tig]);
                ah[2] = __float_as_uint(sAh[r       * SA_STR + k0 + tig + 4]);
                ah[3] = __float_as_uint(sAh[(r + 8) * SA_STR + k0 + tig + 4]);
                al[0] = __float_as_uint(sAl[r       * SA_STR + k0 + tig]);
                al[1] = __float_as_uint(sAl[(r + 8) * SA_STR + k0 + tig]);
                al[2] = __float_as_uint(sAl[r       * SA_STR + k0 + tig + 4]);
                al[3] = __float_as_uint(sAl[(r + 8) * SA_STR + k0 + tig + 4]);
                #pragma unroll
                for (int nt = 0; nt < 8; nt++) {
                    mma_tf32(acc[mt][nt], ah, bh[nt]);
                    mma_tf32(acc[mt][nt], ah, bl[nt]);
                    mma_tf32(acc[mt][nt], al, bh[nt]);
                }
            }
        }
    }

    #pragma unroll
    for (int mt = 0; mt < 2; mt++) {
        #pragma unroll
        for (int rh = 0; rh < 2; rh++) {
            int m = m0 + warp * 32 + mt * 16 + rh * 8 + gid;
            float* dst = g_X1 + (size_t)m * GC_HID + n0;
            #pragma unroll
            for (int nt = 0; nt < 8; nt++) {
                int col = nt * 8 + tig * 2;
                *(float2*)(dst + col) =
                    make_float2(acc[mt][nt][rh * 2 + 0], acc[mt][nt][rh * 2 + 1]);
            }
        }
    }
}

// ---------------- K5: SpMM + leaky + fused gc2 dot ----------------
__global__ __launch_bounds__(256) void spmm_kernel(const float* __restrict__ gc2, int E) {
    int warp = threadIdx.x >> 5, lane = threadIdx.x & 31;
    int n = blockIdx.x * 8 + warp;
    int b = blockIdx.y;
    int s = g_rowptr[b * (Nn + 1) + n];
    int t = g_rowptr[b * (Nn + 1) + n + 1];
    float a0 = 0, a1 = 0, a2 = 0, a3 = 0;
    const float* Xb = g_X1 + (size_t)b * Nn * GC_HID;
    for (int k = s; k < t; k++) {
        float w = g_vals[b * E_MAX + k];
        int   c = g_cols[b * E_MAX + k];
        const float* xr = Xb + (size_t)c * GC_HID + lane;
        a0 += w * xr[0];
        a1 += w * xr[32];
        a2 += w * xr[64];
        a3 += w * xr[96];
    }
    a0 = (a0 > 0.f) ? a0 : 0.2f * a0;
    a1 = (a1 > 0.f) ? a1 : 0.2f * a1;
    a2 = (a2 > 0.f) ? a2 : 0.2f * a2;
    a3 = (a3 > 0.f) ? a3 : 0.2f * a3;
    float p = a0 * gc2[lane] + a1 * gc2[lane + 32] + a2 * gc2[lane + 64] + a3 * gc2[lane + 96];
    #pragma unroll
    for (int o = 16; o; o >>= 1) p += __shfl_xor_sync(0xffffffffu, p, o);
    if (lane == 0) g_X2[b * Nn + n] = p;
}

__global__ void finalize_kernel(float* __restrict__ out, int E) {
    int idx = blockIdx.x * blockDim.x + threadIdx.x;
    if (idx >= Bsz * Nn) return;
    int b = idx / Nn, n = idx % Nn;
    int s = g_rowptr[b * (Nn + 1) + n];
    int t = g_rowptr[b * (Nn + 1) + n + 1];
    float acc = 0.f;
    for (int k = s; k < t; k++)
        acc += g_vals[b * E_MAX + k] * g_X2[b * Nn + g_cols[b * E_MAX + k]];
    out[idx] = 1.f / (1.f + expf(-acc));
}

// ---------------- launch ----------------
extern "C" void kernel_launch(void* const* d_in, const int* in_sizes, int n_in,
                              void* d_out, int out_size) {
    const float* search = (const float*)d_in[0];
    const float* xcorr  = (const float*)d_in[1];
    const int*   pairs  = (const int*)d_in[2];
    const float* phi_w1 = (const float*)d_in[3];
    const float* phi_b1 = (const float*)d_in[4];
    const float* gamma  = (const float*)d_in[5];
    const float* beta   = (const float*)d_in[6];
    const float* phi_w2 = (const float*)d_in[7];
    const float* phi_b2 = (const float*)d_in[8];
    const float* gc1_w  = (const float*)d_in[9];
    const float* gc2_w  = (const float*)d_in[10];
    float* out = (float*)d_out;

    int E = in_sizes[2] / (2 * Bsz);
    if (E > E_MAX) E = E_MAX;

    zero_kernel<<<(Bsz * Nn + 255) / 256, 256>>>();
    wsplit_kernel<<<(Cc * GC_HID + 255) / 256, 256>>>(phi_w1, gc1_w);
    transpose_kernel<<<dim3(Nn / 32, Cc / 32, Bsz), dim3(32, 32)>>>(search, xcorr);
    phi_mma_kernel<<<dim3((E + BLK_E - 1) / BLK_E, Bsz), 128>>>(pairs, phi_b1, E);
    edge_weight_kernel<<<dim3((E + 255) / 256, Bsz), 256>>>(gamma, beta, phi_w2, phi_b2, E);
    count_kernel<<<(Bsz * E + 255) / 256, 256>>>(pairs, E);
    scan_kernel<<<Bsz, 1024>>>(E);
    scatter_kernel<<<(Bsz * E + 255) / 256, 256>>>(pairs, E);
    x1_mma_kernel<<<dim3((Bsz * Nn) / 128, GC_HID / 64), 128>>>();
    spmm_kernel<<<dim3(Nn / 8, Bsz), 256>>>(gc2_w, E);
    finalize_kernel<<<(Bsz * Nn + 255) / 256, 256>>>(out, E);
}

// round 5
// speedup vs baseline: 1.2689x; 1.1389x over previous
#include <cuda_runtime.h>
#include <cuda_bf16.h>
#include <math.h>
#include <cstdint>

#define Bsz       16
#define Nn        1024
#define C_SEARCH  256
#define C_XCORR   64
#define Cc        320
#define PHI_H     64
#define GC_HID    128
#define E_MAX     10068
#define BN_EPS    1e-5f
#define BLK_E     128
#define NCHUNK    20          // Cc / 16
#define KCHUNK    16
#define SA_STR    20
#define SW_STR    72

// phi smem layout (float4 units)
#define WBUF_F4   528         // 8 planes * 66
#define ABUF_F4   1040        // 8 planes * 130
#define SMEM_F4   (2*WBUF_F4 + 2*ABUF_F4)            // 3136
#define PHI_SMEM_BYTES  (SMEM_F4*16 + 192*4)         // 50944

// ---------------- scratch ----------------
__device__ __align__(16) float g_featT[Bsz * Nn * Cc];
__device__ float4 g_w1P[NCHUNK * 512];       // packed (hi,hi+4,lo,lo+4) per (chunk,plane,n)
__device__ float g_gwhi[Cc * GC_HID];
__device__ float g_gwlo[Cc * GC_HID];
__device__ __align__(16) float g_h[Bsz * E_MAX * PHI_H];
__device__ float g_bn_sum[Bsz * PHI_H];
__device__ float g_bn_sumsq[Bsz * PHI_H];
__device__ float g_edgew[Bsz * E_MAX];
__device__ int   g_deg[Bsz * Nn];
__device__ int   g_rowptr[Bsz * (Nn + 1)];
__device__ int   g_cursor[Bsz * Nn];
__device__ int   g_cols[Bsz * E_MAX];
__device__ float g_vals[Bsz * E_MAX];
__device__ __align__(16) float g_X1[Bsz * Nn * GC_HID];
__device__ float g_X2[Bsz * Nn];

__device__ __forceinline__ float to_tf32(float x) {
    float y; asm("cvt.rna.tf32.f32 %0, %1;" : "=f"(y) : "f"(x)); return y;
}
__device__ __forceinline__ uint32_t fau(float x) { return __float_as_uint(x); }

__device__ __forceinline__ void mma_tf32(float* d, const uint32_t* a, const uint32_t* b) {
    asm volatile(
        "mma.sync.aligned.m16n8k8.row.col.f32.tf32.tf32.f32 "
        "{%0,%1,%2,%3}, {%4,%5,%6,%7}, {%8,%9}, {%0,%1,%2,%3};"
        : "+f"(d[0]), "+f"(d[1]), "+f"(d[2]), "+f"(d[3])
        : "r"(a[0]), "r"(a[1]), "r"(a[2]), "r"(a[3]), "r"(b[0]), "r"(b[1]));
}

__device__ __forceinline__ uint32_t smem_u32_of(const void* p) {
    uint32_t a;
    asm("{ .reg .u64 t; cvta.to.shared.u64 t, %1; cvt.u32.u64 %0, t; }" : "=r"(a) : "l"(p));
    return a;
}
__device__ __forceinline__ void cp_async16(uint32_t dst, const void* src) {
    asm volatile("cp.async.ca.shared.global [%0], [%1], 16;" :: "r"(dst), "l"(src));
}
#define CP_COMMIT() asm volatile("cp.async.commit_group;" ::: "memory")
#define CP_WAIT0()  asm volatile("cp.async.wait_group 0;" ::: "memory")

// ---------------- small kernels ----------------
__global__ void zero_kernel() {
    int i = blockIdx.x * blockDim.x + threadIdx.x;
    if (i < Bsz * Nn) g_deg[i] = 0;
    if (i < Bsz * PHI_H) { g_bn_sum[i] = 0.f; g_bn_sumsq[i] = 0.f; }
}

// build packed W1 planes + split gc1_w
__global__ void wsplit_kernel(const float* __restrict__ w1,
                              const float* __restrict__ gw) {
    int i = blockIdx.x * blockDim.x + threadIdx.x;
    if (i < NCHUNK * 512) {
        int c = i >> 9, rem = i & 511, pl = rem >> 6, n = rem & 63;
        int ks = pl >> 2, tg = pl & 3;
        int k1 = c * 16 + ks * 8 + tg, k2 = k1 + 4;
        float wa = w1[k1 * 64 + n], wb = w1[k2 * 64 + n];
        float ha = to_tf32(wa), hb = to_tf32(wb);
        g_w1P[i] = make_float4(ha, hb, to_tf32(wa - ha), to_tf32(wb - hb));
    }
    if (i < Cc * GC_HID) {
        float v = gw[i];
        float hi = to_tf32(v);
        g_gwhi[i] = hi;
        g_gwlo[i] = to_tf32(v - hi);
    }
}

__global__ void transpose_kernel(const float* __restrict__ search,
                                 const float* __restrict__ xcorr) {
    __shared__ float tile[32][33];
    int b  = blockIdx.z;
    int c0 = blockIdx.y * 32;
    int n0 = blockIdx.x * 32;
    int tx = threadIdx.x, ty = threadIdx.y;
    int c = c0 + ty, n = n0 + tx;
    float v;
    if (c < C_SEARCH) v = search[((size_t)b * C_SEARCH + c) * Nn + n];
    else              v = xcorr[((size_t)b * C_XCORR + (c - C_SEARCH)) * Nn + n];
    tile[ty][tx] = v;
    __syncthreads();
    g_featT[((size_t)b * Nn + n0 + ty) * Cc + c0 + tx] = tile[tx][ty];
}

// ---------------- K1: phi GEMM, 3xTF32, double-buffered, packed frags ----------------
__global__ __launch_bounds__(128) void phi_mma_kernel(
        const int* __restrict__ pairs, const float* __restrict__ b1, int E) {
    extern __shared__ float4 smem4[];
    float4* sW = smem4;                 // [2][528]
    float4* sA = smem4 + 2 * WBUF_F4;   // [2][1040]
    float* sBias = (float*)(smem4 + SMEM_F4);
    float* sSum  = sBias + 64;
    float* sSq   = sBias + 128;

    int tid = threadIdx.x, warp = tid >> 5, lane = tid & 31;
    int gid = lane >> 2, tig = lane & 3;
    int b = blockIdx.y, e0 = blockIdx.x * BLK_E;

    if (tid < 64) { sBias[tid] = b1[tid]; sSum[tid] = 0.f; sSq[tid] = 0.f; }

    int e = e0 + tid;
    int2 p = (e < E) ? ((const int2*)pairs)[(size_t)b * E + e] : make_int2(0, 0);
    const float4* rowx = (const float4*)(g_featT + (size_t)b * Nn * Cc + (size_t)p.x * Cc);
    const float4* rowy = (const float4*)(g_featT + (size_t)b * Nn * Cc + (size_t)p.y * Cc);

    uint32_t smem_base = smem_u32_of(smem4);

    float4 xr[4], yr[4];
    float acc[2][8][4] = {};

    // ---- prologue: chunk 0 ----
    {
        const float4* src = g_w1P;
        #pragma unroll
        for (int i = 0; i < 4; i++) {
            int idx = tid + i * 128;
            int pl = idx >> 6, n = idx & 63;
            cp_async16(smem_base + (uint32_t)(pl * 66 + n) * 16u, src + idx);
        }
        CP_COMMIT();
        #pragma unroll
        for (int j = 0; j < 4; j++) { xr[j] = rowx[j]; yr[j] = rowy[j]; }
        const float* xs = (const float*)xr;
        const float* ys = (const float*)yr;
        #pragma unroll
        for (int ks = 0; ks < 2; ks++)
            #pragma unroll
            for (int tg = 0; tg < 4; tg++) {
                int k1 = ks * 8 + tg, k2 = k1 + 4;
                float d1 = fabsf(xs[k1] - ys[k1]);
                float d2 = fabsf(xs[k2] - ys[k2]);
                float h1 = to_tf32(d1), h2 = to_tf32(d2);
                sA[(ks * 4 + tg) * 130 + tid] =
                    make_float4(h1, h2, to_tf32(d1 - h1), to_tf32(d2 - h2));
            }
        CP_WAIT0();
    }
    __syncthreads();

    // ---- main loop ----
    for (int c = 0; c < NCHUNK; c++) {
        int cur = c & 1, nxt = cur ^ 1;
        bool more = (c + 1 < NCHUNK);
        if (more) {
            const float4* src = g_w1P + (c + 1) * 512;
            #pragma unroll
            for (int i = 0; i < 4; i++) {
                int idx = tid + i * 128;
                int pl = idx >> 6, n = idx & 63;
                cp_async16(smem_base + (uint32_t)(nxt * WBUF_F4 + pl * 66 + n) * 16u, src + idx);
            }
            CP_COMMIT();
            #pragma unroll
            for (int j = 0; j < 4; j++) {
                xr[j] = rowx[(c + 1) * 4 + j];
                yr[j] = rowy[(c + 1) * 4 + j];
            }
        }
        // MMA on chunk c
        #pragma unroll
        for (int ks = 0; ks < 2; ks++) {
            float4 bf[8];
            #pragma unroll
            for (int nt = 0; nt < 8; nt++)
                bf[nt] = sW[cur * WBUF_F4 + (ks * 4 + tig) * 66 + nt * 8 + gid];
            #pragma unroll
            for (int mt = 0; mt < 2; mt++) {
                int r = warp * 32 + mt * 16 + gid;
                float4 a0 = sA[cur * ABUF_F4 + (ks * 4 + tig) * 130 + r];
                float4 a1 = sA[cur * ABUF_F4 + (ks * 4 + tig) * 130 + r + 8];
                uint32_t ah[4] = { fau(a0.x), fau(a1.x), fau(a0.y), fau(a1.y) };
                uint32_t al[4] = { fau(a0.z), fau(a1.z), fau(a0.w), fau(a1.w) };
                #pragma unroll
                for (int nt = 0; nt < 8; nt++) {
                    uint32_t bh[2] = { fau(bf[nt].x), fau(bf[nt].y) };
                    uint32_t bl[2] = { fau(bf[nt].z), fau(bf[nt].w) };
                    mma_tf32(acc[mt][nt], ah, bh);
                    mma_tf32(acc[mt][nt], ah, bl);
                    mma_tf32(acc[mt][nt], al, bh);
                }
            }
        }
        if (more) {
            const float* xs = (const float*)xr;
            const float* ys = (const float*)yr;
            #pragma unroll
            for (int ks = 0; ks < 2; ks++)
                #pragma unroll
                for (int tg = 0; tg < 4; tg++) {
                    int k1 = ks * 8 + tg, k2 = k1 + 4;
                    float d1 = fabsf(xs[k1] - ys[k1]);
                    float d2 = fabsf(xs[k2] - ys[k2]);
                    float h1 = to_tf32(d1), h2 = to_tf32(d2);
                    sA[nxt * ABUF_F4 + (ks * 4 + tg) * 130 + tid] =
                        make_float4(h1, h2, to_tf32(d1 - h1), to_tf32(d2 - h2));
                }
            CP_WAIT0();
        }
        __syncthreads();
    }

    // ---- epilogue: bias, store h, BN partial sums ----
    float ts[8][2] = {}, tq[8][2] = {};
    #pragma unroll
    for (int mt = 0; mt < 2; mt++) {
        #pragma unroll
        for (int rh = 0; rh < 2; rh++) {
            int el = warp * 32 + mt * 16 + rh * 8 + gid;
            int e2 = e0 + el;
            bool valid = (e2 < E);
            float* dst = g_h + (((size_t)b * E_MAX) + e2) * PHI_H;
            #pragma unroll
            for (int nt = 0; nt < 8; nt++) {
                int col = nt * 8 + tig * 2;
                float v0 = acc[mt][nt][rh * 2 + 0] + sBias[col];
                float v1 = acc[mt][nt][rh * 2 + 1] + sBias[col + 1];
                if (valid) {
                    *(float2*)(dst + col) = make_float2(v0, v1);
                    ts[nt][0] += v0; tq[nt][0] += v0 * v0;
                    ts[nt][1] += v1; tq[nt][1] += v1 * v1;
                }
            }
        }
    }
    #pragma unroll
    for (int nt = 0; nt < 8; nt++) {
        #pragma unroll
        for (int j = 0; j < 2; j++) {
            float s = ts[nt][j], q = tq[nt][j];
            #pragma unroll
            for (int o = 4; o < 32; o <<= 1) {
                s += __shfl_xor_sync(0xffffffffu, s, o);
                q += __shfl_xor_sync(0xffffffffu, q, o);
            }
            if (gid == 0) {
                int col = nt * 8 + tig * 2 + j;
                atomicAdd(&sSum[col], s);
                atomicAdd(&sSq[col], q);
            }
        }
    }
    __syncthreads();
    if (tid < 64) {
        atomicAdd(&g_bn_sum[b * PHI_H + tid], sSum[tid]);
        atomicAdd(&g_bn_sumsq[b * PHI_H + tid], sSq[tid]);
    }
}

// ---------------- K2: BN + ReLU + Linear + sigmoid ----------------
__global__ __launch_bounds__(256) void edge_weight_kernel(
        const float* __restrict__ gamma, const float* __restrict__ beta,
        const float* __restrict__ w2, const float* __restrict__ b2, int E) {
    int b = blockIdx.y;
    __shared__ __align__(16) float sa[64], sc[64], sw2[64];
    int tid = threadIdx.x;
    if (tid < 64) {
        float mu  = g_bn_sum[b * PHI_H + tid] / (float)E;
        float var = g_bn_sumsq[b * PHI_H + tid] / (float)E - mu * mu;
        var = fmaxf(var, 0.f);
        float inv = rsqrtf(var + BN_EPS);
        float a = gamma[tid] * inv;
        sa[tid] = a;
        sc[tid] = beta[tid] - mu * a;
        sw2[tid] = w2[tid];
    }
    __syncthreads();
    int warp = tid >> 5, lane = tid & 31;
    int sub = lane >> 4, l16 = lane & 15;
    float4 A = *(float4*)&sa[l16 * 4];
    float4 C = *(float4*)&sc[l16 * 4];
    float4 W = *(float4*)&sw2[l16 * 4];
    float bb = b2[0];
    int base = blockIdx.x * 256 + warp * 32;
    #pragma unroll 4
    for (int it = 0; it < 16; it++) {
        int e = base + it * 2 + sub;
        if (e >= E) continue;
        float4 h4 = *(const float4*)(g_h + (((size_t)b * E_MAX) + e) * PHI_H + l16 * 4);
        float p = fmaxf(A.x * h4.x + C.x, 0.f) * W.x
                + fmaxf(A.y * h4.y + C.y, 0.f) * W.y
                + fmaxf(A.z * h4.z + C.z, 0.f) * W.z
                + fmaxf(A.w * h4.w + C.w, 0.f) * W.w;
        #pragma unroll
        for (int o = 8; o; o >>= 1) p += __shfl_xor_sync(0xffffffffu, p, o);
        if (l16 == 0) {
            float z = p + bb;
            g_edgew[b * E_MAX + e] = 1.f / (1.f + expf(-z));
        }
    }
}

// ---------------- CSR build ----------------
__global__ void count_kernel(const int* __restrict__ pairs, int E) {
    int idx = blockIdx.x * blockDim.x + threadIdx.x;
    if (idx >= Bsz * E) return;
    int b = idx / E, e = idx % E;
    atomicAdd(&g_deg[b * Nn + pairs[((size_t)b * E + e) * 2]], 1);
}

__global__ __launch_bounds__(1024) void scan_kernel(int E) {
    int b = blockIdx.x, tid = threadIdx.x;
    int v = g_deg[b * Nn + tid];
    int x = v;
    #pragma unroll
    for (int o = 1; o < 32; o <<= 1) {
        int y = __shfl_up_sync(0xffffffffu, x, o);
        if ((tid & 31) >= o) x += y;
    }
    __shared__ int wsum[32];
    if ((tid & 31) == 31) wsum[tid >> 5] = x;
    __syncthreads();
    if (tid < 32) {
        int y = wsum[tid];
        #pragma unroll
        for (int o = 1; o < 32; o <<= 1) {
            int z = __shfl_up_sync(0xffffffffu, y, o);
            if (tid >= o) y += z;
        }
        wsum[tid] = y;
    }
    __syncthreads();
    int incl = x + ((tid >= 32) ? wsum[(tid >> 5) - 1] : 0);
    int excl = incl - v;
    g_rowptr[b * (Nn + 1) + tid] = excl;
    g_cursor[b * Nn + tid] = excl;
    if (tid == Nn - 1) g_rowptr[b * (Nn + 1) + Nn] = incl;
}

__global__ void scatter_kernel(const int* __restrict__ pairs, int E) {
    int idx = blockIdx.x * blockDim.x + threadIdx.x;
    if (idx >= Bsz * E) return;
    int b = idx / E, e = idx % E;
    int p0 = pairs[((size_t)b * E + e) * 2 + 0];
    int p1 = pairs[((size_t)b * E + e) * 2 + 1];
    int pos = atomicAdd(&g_cursor[b * Nn + p0], 1);
    g_cols[b * E_MAX + pos] = p1;
    g_vals[b * E_MAX + pos] = g_edgew[b * E_MAX + e];
}

// ---------------- K4: X1 = featT @ gc1_w via 3xTF32 ----------------
__global__ __launch_bounds__(128) void x1_mma_kernel() {
    __shared__ float sAh[128 * SA_STR];
    __shared__ float sAl[128 * SA_STR];
    __shared__ float sWh[KCHUNK * SW_STR];
    __shared__ float sWl[KCHUNK * SW_STR];

    int tid = threadIdx.x, warp = tid >> 5, lane = tid & 31;
    int gid = lane >> 2, tig = lane & 3;
    int m0 = blockIdx.x * 128;
    int n0 = blockIdx.y * 64;

    float acc[2][8][4] = {};

    for (int kc = 0; kc < Cc; kc += KCHUNK) {
        __syncthreads();
        #pragma unroll
        for (int i = 0; i < 4; i++) {
            int idx = tid + i * 128;
            int row = idx >> 2, c4 = idx & 3;
            float4 a = *(const float4*)(g_featT + (size_t)(m0 + row) * Cc + kc + c4 * 4);
            float4 ah4, al4;
            ah4.x = to_tf32(a.x); al4.x = to_tf32(a.x - ah4.x);
            ah4.y = to_tf32(a.y); al4.y = to_tf32(a.y - ah4.y);
            ah4.z = to_tf32(a.z); al4.z = to_tf32(a.z - ah4.z);
            ah4.w = to_tf32(a.w); al4.w = to_tf32(a.w - ah4.w);
            *(float4*)&sAh[row * SA_STR + c4 * 4] = ah4;
            *(float4*)&sAl[row * SA_STR + c4 * 4] = al4;
        }
        #pragma unroll
        for (int i = 0; i < 2; i++) {
            int idx = tid + i * 128;
            int row = idx >> 4, c4 = idx & 15;
            float4 wh = *(const float4*)(g_gwhi + (size_t)(kc + row) * GC_HID + n0 + c4 * 4);
            float4 wl = *(const float4*)(g_gwlo + (size_t)(kc + row) * GC_HID + n0 + c4 * 4);
            *(float4*)&sWh[row * SW_STR + c4 * 4] = wh;
            *(float4*)&sWl[row * SW_STR + c4 * 4] = wl;
        }
        __syncthreads();

        #pragma unroll
        for (int ks = 0; ks < 2; ks++) {
            int k0 = ks * 8;
            uint32_t bh[8][2], bl[8][2];
            #pragma unroll
            for (int nt = 0; nt < 8; nt++) {
                int c = nt * 8 + gid;
                bh[nt][0] = fau(sWh[(k0 + tig)     * SW_STR + c]);
                bh[nt][1] = fau(sWh[(k0 + tig + 4) * SW_STR + c]);
                bl[nt][0] = fau(sWl[(k0 + tig)     * SW_STR + c]);
                bl[nt][1] = fau(sWl[(k0 + tig + 4) * SW_STR + c]);
            }
            #pragma unroll
            for (int mt = 0; mt < 2; mt++) {
                int r = warp * 32 + mt * 16 + gid;
                uint32_t ah[4], al[4];
                ah[0] = fau(sAh[r       * SA_STR + k0 + tig]);
                ah[1] = fau(sAh[(r + 8) * SA_STR + k0 + tig]);
                ah[2] = fau(sAh[r       * SA_STR + k0 + tig + 4]);
                ah[3] = fau(sAh[(r + 8) * SA_STR + k0 + tig + 4]);
                al[0] = fau(sAl[r       * SA_STR + k0 + tig]);
                al[1] = fau(sAl[(r + 8) * SA_STR + k0 + tig]);
                al[2] = fau(sAl[r       * SA_STR + k0 + tig + 4]);
                al[3] = fau(sAl[(r + 8) * SA_STR + k0 + tig + 4]);
                #pragma unroll
                for (int nt = 0; nt < 8; nt++) {
                    mma_tf32(acc[mt][nt], ah, bh[nt]);
                    mma_tf32(acc[mt][nt], ah, bl[nt]);
                    mma_tf32(acc[mt][nt], al, bh[nt]);
                }
            }
        }
    }

    #pragma unroll
    for (int mt = 0; mt < 2; mt++) {
        #pragma unroll
        for (int rh = 0; rh < 2; rh++) {
            int m = m0 + warp * 32 + mt * 16 + rh * 8 + gid;
            float* dst = g_X1 + (size_t)m * GC_HID + n0;
            #pragma unroll
            for (int nt = 0; nt < 8; nt++) {
                int col = nt * 8 + tig * 2;
                *(float2*)(dst + col) =
                    make_float2(acc[mt][nt][rh * 2 + 0], acc[mt][nt][rh * 2 + 1]);
            }
        }
    }
}

// ---------------- K5: SpMM + leaky + fused gc2 dot ----------------
__global__ __launch_bounds__(256) void spmm_kernel(const float* __restrict__ gc2, int E) {
    int warp = threadIdx.x >> 5, lane = threadIdx.x & 31;
    int n = blockIdx.x * 8 + warp;
    int b = blockIdx.y;
    int s = g_rowptr[b * (Nn + 1) + n];
    int t = g_rowptr[b * (Nn + 1) + n + 1];
    float a0 = 0, a1 = 0, a2 = 0, a3 = 0;
    const float* Xb = g_X1 + (size_t)b * Nn * GC_HID;
    for (int k = s; k < t; k++) {
        float w = g_vals[b * E_MAX + k];
        int   c = g_cols[b * E_MAX + k];
        const float* xr = Xb + (size_t)c * GC_HID + lane;
        a0 += w * xr[0];
        a1 += w * xr[32];
        a2 += w * xr[64];
        a3 += w * xr[96];
    }
    a0 = (a0 > 0.f) ? a0 : 0.2f * a0;
    a1 = (a1 > 0.f) ? a1 : 0.2f * a1;
    a2 = (a2 > 0.f) ? a2 : 0.2f * a2;
    a3 = (a3 > 0.f) ? a3 : 0.2f * a3;
    float p = a0 * gc2[lane] + a1 * gc2[lane + 32] + a2 * gc2[lane + 64] + a3 * gc2[lane + 96];
    #pragma unroll
    for (int o = 16; o; o >>= 1) p += __shfl_xor_sync(0xffffffffu, p, o);
    if (lane == 0) g_X2[b * Nn + n] = p;
}

__global__ void finalize_kernel(float* __restrict__ out, int E) {
    int idx = blockIdx.x * blockDim.x + threadIdx.x;
    if (idx >= Bsz * Nn) return;
    int b = idx / Nn, n = idx % Nn;
    int s = g_rowptr[b * (Nn + 1) + n];
    int t = g_rowptr[b * (Nn + 1) + n + 1];
    float acc = 0.f;
    for (int k = s; k < t; k++)
        acc += g_vals[b * E_MAX + k] * g_X2[b * Nn + g_cols[b * E_MAX + k]];
    out[idx] = 1.f / (1.f + expf(-acc));
}

// ---------------- launch ----------------
extern "C" void kernel_launch(void* const* d_in, const int* in_sizes, int n_in,
                              void* d_out, int out_size) {
    const float* search = (const float*)d_in[0];
    const float* xcorr  = (const float*)d_in[1];
    const int*   pairs  = (const int*)d_in[2];
    const float* phi_w1 = (const float*)d_in[3];
    const float* phi_b1 = (const float*)d_in[4];
    const float* gamma  = (const float*)d_in[5];
    const float* beta   = (const float*)d_in[6];
    const float* phi_w2 = (const float*)d_in[7];
    const float* phi_b2 = (const float*)d_in[8];
    const float* gc1_w  = (const float*)d_in[9];
    const float* gc2_w  = (const float*)d_in[10];
    float* out = (float*)d_out;

    int E = in_sizes[2] / (2 * Bsz);
    if (E > E_MAX) E = E_MAX;

    cudaFuncSetAttribute(phi_mma_kernel,
                         cudaFuncAttributeMaxDynamicSharedMemorySize, PHI_SMEM_BYTES);

    zero_kernel<<<(Bsz * Nn + 255) / 256, 256>>>();
    wsplit_kernel<<<(Cc * GC_HID + 255) / 256, 256>>>(phi_w1, gc1_w);
    transpose_kernel<<<dim3(Nn / 32, Cc / 32, Bsz), dim3(32, 32)>>>(search, xcorr);
    phi_mma_kernel<<<dim3((E + BLK_E - 1) / BLK_E, Bsz), 128, PHI_SMEM_BYTES>>>(pairs, phi_b1, E);
    edge_weight_kernel<<<dim3((E + 255) / 256, Bsz), 256>>>(gamma, beta, phi_w2, phi_b2, E);
    count_kernel<<<(Bsz * E + 255) / 256, 256>>>(pairs, E);
    scan_kernel<<<Bsz, 1024>>>(E);
    scatter_kernel<<<(Bsz * E + 255) / 256, 256>>>(pairs, E);
    x1_mma_kernel<<<dim3((Bsz * Nn) / 128, GC_HID / 64), 128>>>();
    spmm_kernel<<<dim3(Nn / 8, Bsz), 256>>>(gc2_w, E);
    finalize_kernel<<<(Bsz * Nn + 255) / 256, 256>>>(out, E);
}

// round 6
// speedup vs baseline: 1.4325x; 1.1289x over previous
#include <cuda_runtime.h>
#include <cuda_bf16.h>
#include <math.h>
#include <cstdint>

#define Bsz       16
#define Nn        1024
#define C_SEARCH  256
#define C_XCORR   64
#define Cc        320
#define PHI_H     64
#define GC_HID    128
#define E_MAX     10068
#define BN_EPS    1e-5f
#define BLK_E     128
#define NCHUNK    20          // Cc / 16
#define KCHUNK    16
#define SA_STR    20
#define SW_STR    72

// phi smem (float4 units): W buf 4 planes * 66, A buf 4 planes * 130
#define WBUF_F4   264
#define ABUF_F4   520
#define SMEM_F4   (2*WBUF_F4 + 2*ABUF_F4)           // 1568
#define PHI_SMEM_BYTES  (SMEM_F4*16 + 192*4)        // 25856

// ---------------- scratch ----------------
__device__ __align__(16) float g_featT[Bsz * Nn * Cc];
__device__ uint4 g_w1P[NCHUNK * 256];        // bf16-packed W1: [chunk][plane(4)][n(64)]
__device__ float g_gwhi[Cc * GC_HID];
__device__ float g_gwlo[Cc * GC_HID];
__device__ __align__(16) float g_h[Bsz * E_MAX * PHI_H];
__device__ float g_bn_sum[Bsz * PHI_H];
__device__ float g_bn_sumsq[Bsz * PHI_H];
__device__ float g_edgew[Bsz * E_MAX];
__device__ int   g_deg[Bsz * Nn];
__device__ int   g_rowptr[Bsz * (Nn + 1)];
__device__ int   g_cursor[Bsz * Nn];
__device__ int   g_cols[Bsz * E_MAX];
__device__ float g_vals[Bsz * E_MAX];
__device__ __align__(16) float g_X1[Bsz * Nn * GC_HID];
__device__ float g_X2[Bsz * Nn];

__device__ __forceinline__ float to_tf32(float x) {
    float y; asm("cvt.rna.tf32.f32 %0, %1;" : "=f"(y) : "f"(x)); return y;
}
__device__ __forceinline__ uint32_t fau(float x) { return __float_as_uint(x); }

// pack two floats into bf16x2 (lo = first element, hi = second)
__device__ __forceinline__ uint32_t pack_bf(float lo, float hi) {
    uint32_t r;
    asm("cvt.rn.bf16x2.f32 %0, %1, %2;" : "=r"(r) : "f"(hi), "f"(lo));
    return r;
}
__device__ __forceinline__ float bf_round(float x) {
    return __bfloat162float(__float2bfloat16_rn(x));
}

__device__ __forceinline__ void mma_bf16(float* d, const uint32_t* a, const uint32_t* b) {
    asm volatile(
        "mma.sync.aligned.m16n8k16.row.col.f32.bf16.bf16.f32 "
        "{%0,%1,%2,%3}, {%4,%5,%6,%7}, {%8,%9}, {%0,%1,%2,%3};"
        : "+f"(d[0]), "+f"(d[1]), "+f"(d[2]), "+f"(d[3])
        : "r"(a[0]), "r"(a[1]), "r"(a[2]), "r"(a[3]), "r"(b[0]), "r"(b[1]));
}
__device__ __forceinline__ void mma_tf32(float* d, const uint32_t* a, const uint32_t* b) {
    asm volatile(
        "mma.sync.aligned.m16n8k8.row.col.f32.tf32.tf32.f32 "
        "{%0,%1,%2,%3}, {%4,%5,%6,%7}, {%8,%9}, {%0,%1,%2,%3};"
        : "+f"(d[0]), "+f"(d[1]), "+f"(d[2]), "+f"(d[3])
        : "r"(a[0]), "r"(a[1]), "r"(a[2]), "r"(a[3]), "r"(b[0]), "r"(b[1]));
}

__device__ __forceinline__ uint32_t smem_u32_of(const void* p) {
    uint32_t a;
    asm("{ .reg .u64 t; cvta.to.shared.u64 t, %1; cvt.u32.u64 %0, t; }" : "=r"(a) : "l"(p));
    return a;
}
__device__ __forceinline__ void cp_async16(uint32_t dst, const void* src) {
    asm volatile("cp.async.ca.shared.global [%0], [%1], 16;" :: "r"(dst), "l"(src));
}
#define CP_COMMIT() asm volatile("cp.async.commit_group;" ::: "memory")
#define CP_WAIT0()  asm volatile("cp.async.wait_group 0;" ::: "memory")

// ---------------- small kernels ----------------
__global__ void zero_kernel() {
    int i = blockIdx.x * blockDim.x + threadIdx.x;
    if (i < Bsz * Nn) g_deg[i] = 0;
    if (i < Bsz * PHI_H) { g_bn_sum[i] = 0.f; g_bn_sumsq[i] = 0.f; }
}

// pack W1 bf16 hi/lo planes + split gc1_w (tf32)
__global__ void wsplit_kernel(const float* __restrict__ w1,
                              const float* __restrict__ gw) {
    int i = blockIdx.x * blockDim.x + threadIdx.x;
    if (i < NCHUNK * 256) {
        int c = i >> 8, rem = i & 255, t = rem >> 6, n = rem & 63;
        int kb = c * 16 + t * 2;
        float w0 = w1[(kb    ) * 64 + n];
        float w1v= w1[(kb + 1) * 64 + n];
        float w8 = w1[(kb + 8) * 64 + n];
        float w9 = w1[(kb + 9) * 64 + n];
        float h0 = bf_round(w0), h1 = bf_round(w1v), h8 = bf_round(w8), h9 = bf_round(w9);
        uint4 o;
        o.x = pack_bf(h0, h1);
        o.y = pack_bf(h8, h9);
        o.z = pack_bf(w0 - h0, w1v - h1);
        o.w = pack_bf(w8 - h8, w9 - h9);
        g_w1P[i] = o;
    }
    if (i < Cc * GC_HID) {
        float v = gw[i];
        float hi = to_tf32(v);
        g_gwhi[i] = hi;
        g_gwlo[i] = to_tf32(v - hi);
    }
}

__global__ void transpose_kernel(const float* __restrict__ search,
                                 const float* __restrict__ xcorr) {
    __shared__ float tile[32][33];
    int b  = blockIdx.z;
    int c0 = blockIdx.y * 32;
    int n0 = blockIdx.x * 32;
    int tx = threadIdx.x, ty = threadIdx.y;
    int c = c0 + ty, n = n0 + tx;
    float v;
    if (c < C_SEARCH) v = search[((size_t)b * C_SEARCH + c) * Nn + n];
    else              v = xcorr[((size_t)b * C_XCORR + (c - C_SEARCH)) * Nn + n];
    tile[ty][tx] = v;
    __syncthreads();
    g_featT[((size_t)b * Nn + n0 + ty) * Cc + c0 + tx] = tile[tx][ty];
}

// ---------------- K1: phi GEMM, bf16 2-term split, double-buffered ----------------
__global__ __launch_bounds__(128) void phi_mma_kernel(
        const int* __restrict__ pairs, const float* __restrict__ b1, int E) {
    extern __shared__ uint4 smem4[];
    uint4* sW = smem4;                  // [2][264]
    uint4* sA = smem4 + 2 * WBUF_F4;    // [2][520]
    float* sBias = (float*)(smem4 + SMEM_F4);
    float* sSum  = sBias + 64;
    float* sSq   = sBias + 128;

    int tid = threadIdx.x, warp = tid >> 5, lane = tid & 31;
    int gid = lane >> 2, tig = lane & 3;
    int b = blockIdx.y, e0 = blockIdx.x * BLK_E;

    if (tid < 64) { sBias[tid] = b1[tid]; sSum[tid] = 0.f; sSq[tid] = 0.f; }

    int e = e0 + tid;
    int2 p = (e < E) ? ((const int2*)pairs)[(size_t)b * E + e] : make_int2(0, 0);
    const float4* rowx = (const float4*)(g_featT + (size_t)b * Nn * Cc + (size_t)p.x * Cc);
    const float4* rowy = (const float4*)(g_featT + (size_t)b * Nn * Cc + (size_t)p.y * Cc);

    uint32_t smem_base = smem_u32_of(smem4);

    float4 xr[4], yr[4];
    float acc[2][8][4] = {};

    // pack 16 diffs into 4 plane-uint4s and store
    auto pack_store = [&](int buf) {
        const float* xs = (const float*)xr;
        const float* ys = (const float*)yr;
        #pragma unroll
        for (int t = 0; t < 4; t++) {
            float d0 = fabsf(xs[2*t]   - ys[2*t]);
            float d1 = fabsf(xs[2*t+1] - ys[2*t+1]);
            float d8 = fabsf(xs[2*t+8] - ys[2*t+8]);
            float d9 = fabsf(xs[2*t+9] - ys[2*t+9]);
            float h0 = bf_round(d0), h1 = bf_round(d1);
            float h8 = bf_round(d8), h9 = bf_round(d9);
            uint4 o;
            o.x = pack_bf(d0 ? h0 : 0.f, d1 ? h1 : 0.f);   // keep exact zeros
            o.y = pack_bf(d8 ? h8 : 0.f, d9 ? h9 : 0.f);
            o.z = pack_bf(d0 - h0, d1 - h1);
            o.w = pack_bf(d8 - h8, d9 - h9);
            sA[buf * ABUF_F4 + t * 130 + tid] = o;
        }
    };

    // ---- prologue: chunk 0 ----
    {
        const uint4* src = g_w1P;
        #pragma unroll
        for (int i = 0; i < 2; i++) {
            int idx = tid + i * 128;
            int pl = idx >> 6, n = idx & 63;
            cp_async16(smem_base + (uint32_t)(pl * 66 + n) * 16u, src + idx);
        }
        CP_COMMIT();
        #pragma unroll
        for (int j = 0; j < 4; j++) { xr[j] = rowx[j]; yr[j] = rowy[j]; }
        pack_store(0);
        CP_WAIT0();
    }
    __syncthreads();

    // ---- main loop ----
    for (int c = 0; c < NCHUNK; c++) {
        int cur = c & 1, nxt = cur ^ 1;
        bool more = (c + 1 < NCHUNK);
        if (more) {
            const uint4* src = g_w1P + (c + 1) * 256;
            #pragma unroll
            for (int i = 0; i < 2; i++) {
                int idx = tid + i * 128;
                int pl = idx >> 6, n = idx & 63;
                cp_async16(smem_base + (uint32_t)(nxt * WBUF_F4 + pl * 66 + n) * 16u, src + idx);
            }
            CP_COMMIT();
            #pragma unroll
            for (int j = 0; j < 4; j++) {
                xr[j] = rowx[(c + 1) * 4 + j];
                yr[j] = rowy[(c + 1) * 4 + j];
            }
        }
        // MMA on chunk c (one k16 step)
        {
            uint4 bf[8];
            #pragma unroll
            for (int nt = 0; nt < 8; nt++)
                bf[nt] = sW[cur * WBUF_F4 + tig * 66 + nt * 8 + gid];
            #pragma unroll
            for (int mt = 0; mt < 2; mt++) {
                int r = warp * 32 + mt * 16 + gid;
                uint4 fA = sA[cur * ABUF_F4 + tig * 130 + r];
                uint4 fB = sA[cur * ABUF_F4 + tig * 130 + r + 8];
                uint32_t ah[4] = { fA.x, fB.x, fA.y, fB.y };
                uint32_t al[4] = { fA.z, fB.z, fA.w, fB.w };
                #pragma unroll
                for (int nt = 0; nt < 8; nt++) {
                    uint32_t bh[2] = { bf[nt].x, bf[nt].y };
                    uint32_t bl[2] = { bf[nt].z, bf[nt].w };
                    mma_bf16(acc[mt][nt], ah, bh);
                    mma_bf16(acc[mt][nt], ah, bl);
                    mma_bf16(acc[mt][nt], al, bh);
                }
            }
        }
        if (more) {
            pack_store(nxt);
            CP_WAIT0();
        }
        __syncthreads();
    }

    // ---- epilogue: bias, store h, BN partial sums ----
    float ts[8][2] = {}, tq[8][2] = {};
    #pragma unroll
    for (int mt = 0; mt < 2; mt++) {
        #pragma unroll
        for (int rh = 0; rh < 2; rh++) {
            int el = warp * 32 + mt * 16 + rh * 8 + gid;
            int e2 = e0 + el;
            bool valid = (e2 < E);
            float* dst = g_h + (((size_t)b * E_MAX) + e2) * PHI_H;
            #pragma unroll
            for (int nt = 0; nt < 8; nt++) {
                int col = nt * 8 + tig * 2;
                float v0 = acc[mt][nt][rh * 2 + 0] + sBias[col];
                float v1 = acc[mt][nt][rh * 2 + 1] + sBias[col + 1];
                if (valid) {
                    *(float2*)(dst + col) = make_float2(v0, v1);
                    ts[nt][0] += v0; tq[nt][0] += v0 * v0;
                    ts[nt][1] += v1; tq[nt][1] += v1 * v1;
                }
            }
        }
    }
    #pragma unroll
    for (int nt = 0; nt < 8; nt++) {
        #pragma unroll
        for (int j = 0; j < 2; j++) {
            float s = ts[nt][j], q = tq[nt][j];
            #pragma unroll
            for (int o = 4; o < 32; o <<= 1) {
                s += __shfl_xor_sync(0xffffffffu, s, o);
                q += __shfl_xor_sync(0xffffffffu, q, o);
            }
            if (gid == 0) {
                int col = nt * 8 + tig * 2 + j;
                atomicAdd(&sSum[col], s);
                atomicAdd(&sSq[col], q);
            }
        }
    }
    __syncthreads();
    if (tid < 64) {
        atomicAdd(&g_bn_sum[b * PHI_H + tid], sSum[tid]);
        atomicAdd(&g_bn_sumsq[b * PHI_H + tid], sSq[tid]);
    }
}

// ---------------- K2: BN + ReLU + Linear + sigmoid ----------------
__global__ __launch_bounds__(256) void edge_weight_kernel(
        const float* __restrict__ gamma, const float* __restrict__ beta,
        const float* __restrict__ w2, const float* __restrict__ b2, int E) {
    int b = blockIdx.y;
    __shared__ __align__(16) float sa[64], sc[64], sw2[64];
    int tid = threadIdx.x;
    if (tid < 64) {
        float mu  = g_bn_sum[b * PHI_H + tid] / (float)E;
        float var = g_bn_sumsq[b * PHI_H + tid] / (float)E - mu * mu;
        var = fmaxf(var, 0.f);
        float inv = rsqrtf(var + BN_EPS);
        float a = gamma[tid] * inv;
        sa[tid] = a;
        sc[tid] = beta[tid] - mu * a;
        sw2[tid] = w2[tid];
    }
    __syncthreads();
    int warp = tid >> 5, lane = tid & 31;
    int sub = lane >> 4, l16 = lane & 15;
    float4 A = *(float4*)&sa[l16 * 4];
    float4 C = *(float4*)&sc[l16 * 4];
    float4 W = *(float4*)&sw2[l16 * 4];
    float bb = b2[0];
    int base = blockIdx.x * 256 + warp * 32;
    #pragma unroll 4
    for (int it = 0; it < 16; it++) {
        int e = base + it * 2 + sub;
        if (e >= E) continue;
        float4 h4 = *(const float4*)(g_h + (((size_t)b * E_MAX) + e) * PHI_H + l16 * 4);
        float p = fmaxf(A.x * h4.x + C.x, 0.f) * W.x
                + fmaxf(A.y * h4.y + C.y, 0.f) * W.y
                + fmaxf(A.z * h4.z + C.z, 0.f) * W.z
                + fmaxf(A.w * h4.w + C.w, 0.f) * W.w;
        #pragma unroll
        for (int o = 8; o; o >>= 1) p += __shfl_xor_sync(0xffffffffu, p, o);
        if (l16 == 0) {
            float z = p + bb;
            g_edgew[b * E_MAX + e] = 1.f / (1.f + expf(-z));
        }
    }
}

// ---------------- CSR build ----------------
__global__ void count_kernel(const int* __restrict__ pairs, int E) {
    int idx = blockIdx.x * blockDim.x + threadIdx.x;
    if (idx >= Bsz * E) return;
    int b = idx / E, e = idx % E;
    atomicAdd(&g_deg[b * Nn + pairs[((size_t)b * E + e) * 2]], 1);
}

__global__ __launch_bounds__(1024) void scan_kernel(int E) {
    int b = blockIdx.x, tid = threadIdx.x;
    int v = g_deg[b * Nn + tid];
    int x = v;
    #pragma unroll
    for (int o = 1; o < 32; o <<= 1) {
        int y = __shfl_up_sync(0xffffffffu, x, o);
        if ((tid & 31) >= o) x += y;
    }
    __shared__ int wsum[32];
    if ((tid & 31) == 31) wsum[tid >> 5] = x;
    __syncthreads();
    if (tid < 32) {
        int y = wsum[tid];
        #pragma unroll
        for (int o = 1; o < 32; o <<= 1) {
            int z = __shfl_up_sync(0xffffffffu, y, o);
            if (tid >= o) y += z;
        }
        wsum[tid] = y;
    }
    __syncthreads();
    int incl = x + ((tid >= 32) ? wsum[(tid >> 5) - 1] : 0);
    int excl = incl - v;
    g_rowptr[b * (Nn + 1) + tid] = excl;
    g_cursor[b * Nn + tid] = excl;
    if (tid == Nn - 1) g_rowptr[b * (Nn + 1) + Nn] = incl;
}

__global__ void scatter_kernel(const int* __restrict__ pairs, int E) {
    int idx = blockIdx.x * blockDim.x + threadIdx.x;
    if (idx >= Bsz * E) return;
    int b = idx / E, e = idx % E;
    int p0 = pairs[((size_t)b * E + e) * 2 + 0];
    int p1 = pairs[((size_t)b * E + e) * 2 + 1];
    int pos = atomicAdd(&g_cursor[b * Nn + p0], 1);
    g_cols[b * E_MAX + pos] = p1;
    g_vals[b * E_MAX + pos] = g_edgew[b * E_MAX + e];
}

// ---------------- K4: X1 = featT @ gc1_w via 3xTF32 ----------------
__global__ __launch_bounds__(128) void x1_mma_kernel() {
    __shared__ float sAh[128 * SA_STR];
    __shared__ float sAl[128 * SA_STR];
    __shared__ float sWh[KCHUNK * SW_STR];
    __shared__ float sWl[KCHUNK * SW_STR];

    int tid = threadIdx.x, warp = tid >> 5, lane = tid & 31;
    int gid = lane >> 2, tig = lane & 3;
    int m0 = blockIdx.x * 128;
    int n0 = blockIdx.y * 64;

    float acc[2][8][4] = {};

    for (int kc = 0; kc < Cc; kc += KCHUNK) {
        __syncthreads();
        #pragma unroll
        for (int i = 0; i < 4; i++) {
            int idx = tid + i * 128;
            int row = idx >> 2, c4 = idx & 3;
            float4 a = *(const float4*)(g_featT + (size_t)(m0 + row) * Cc + kc + c4 * 4);
            float4 ah4, al4;
            ah4.x = to_tf32(a.x); al4.x = to_tf32(a.x - ah4.x);
            ah4.y = to_tf32(a.y); al4.y = to_tf32(a.y - ah4.y);
            ah4.z = to_tf32(a.z); al4.z = to_tf32(a.z - ah4.z);
            ah4.w = to_tf32(a.w); al4.w = to_tf32(a.w - ah4.w);
            *(float4*)&sAh[row * SA_STR + c4 * 4] = ah4;
            *(float4*)&sAl[row * SA_STR + c4 * 4] = al4;
        }
        #pragma unroll
        for (int i = 0; i < 2; i++) {
            int idx = tid + i * 128;
            int row = idx >> 4, c4 = idx & 15;
            float4 wh = *(const float4*)(g_gwhi + (size_t)(kc + row) * GC_HID + n0 + c4 * 4);
            float4 wl = *(const float4*)(g_gwlo + (size_t)(kc + row) * GC_HID + n0 + c4 * 4);
            *(float4*)&sWh[row * SW_STR + c4 * 4] = wh;
            *(float4*)&sWl[row * SW_STR + c4 * 4] = wl;
        }
        __syncthreads();

        #pragma unroll
        for (int ks = 0; ks < 2; ks++) {
            int k0 = ks * 8;
            uint32_t bh[8][2], bl[8][2];
            #pragma unroll
            for (int nt = 0; nt < 8; nt++) {
                int c = nt * 8 + gid;
                bh[nt][0] = fau(sWh[(k0 + tig)     * SW_STR + c]);
                bh[nt][1] = fau(sWh[(k0 + tig + 4) * SW_STR + c]);
                bl[nt][0] = fau(sWl[(k0 + tig)     * SW_STR + c]);
                bl[nt][1] = fau(sWl[(k0 + tig + 4) * SW_STR + c]);
            }
            #pragma unroll
            for (int mt = 0; mt < 2; mt++) {
                int r = warp * 32 + mt * 16 + gid;
                uint32_t ah[4], al[4];
                ah[0] = fau(sAh[r       * SA_STR + k0 + tig]);
                ah[1] = fau(sAh[(r + 8) * SA_STR + k0 + tig]);
                ah[2] = fau(sAh[r       * SA_STR + k0 + tig + 4]);
                ah[3] = fau(sAh[(r + 8) * SA_STR + k0 + tig + 4]);
                al[0] = fau(sAl[r       * SA_STR + k0 + tig]);
                al[1] = fau(sAl[(r + 8) * SA_STR + k0 + tig]);
                al[2] = fau(sAl[r       * SA_STR + k0 + tig + 4]);
                al[3] = fau(sAl[(r + 8) * SA_STR + k0 + tig + 4]);
                #pragma unroll
                for (int nt = 0; nt < 8; nt++) {
                    mma_tf32(acc[mt][nt], ah, bh[nt]);
                    mma_tf32(acc[mt][nt], ah, bl[nt]);
                    mma_tf32(acc[mt][nt], al, bh[nt]);
                }
            }
        }
    }

    #pragma unroll
    for (int mt = 0; mt < 2; mt++) {
        #pragma unroll
        for (int rh = 0; rh < 2; rh++) {
            int m = m0 + warp * 32 + mt * 16 + rh * 8 + gid;
            float* dst = g_X1 + (size_t)m * GC_HID + n0;
            #pragma unroll
            for (int nt = 0; nt < 8; nt++) {
                int col = nt * 8 + tig * 2;
                *(float2*)(dst + col) =
                    make_float2(acc[mt][nt][rh * 2 + 0], acc[mt][nt][rh * 2 + 1]);
            }
        }
    }
}

// ---------------- K5: SpMM + leaky + fused gc2 dot ----------------
__global__ __launch_bounds__(256) void spmm_kernel(const float* __restrict__ gc2, int E) {
    int warp = threadIdx.x >> 5, lane = threadIdx.x & 31;
    int n = blockIdx.x * 8 + warp;
    int b = blockIdx.y;
    int s = g_rowptr[b * (Nn + 1) + n];
    int t = g_rowptr[b * (Nn + 1) + n + 1];
    float a0 = 0, a1 = 0, a2 = 0, a3 = 0;
    const float* Xb = g_X1 + (size_t)b * Nn * GC_HID;
    for (int k = s; k < t; k++) {
        float w = g_vals[b * E_MAX + k];
        int   c = g_cols[b * E_MAX + k];
        const float* xr = Xb + (size_t)c * GC_HID + lane;
        a0 += w * xr[0];
        a1 += w * xr[32];
        a2 += w * xr[64];
        a3 += w * xr[96];
    }
    a0 = (a0 > 0.f) ? a0 : 0.2f * a0;
    a1 = (a1 > 0.f) ? a1 : 0.2f * a1;
    a2 = (a2 > 0.f) ? a2 : 0.2f * a2;
    a3 = (a3 > 0.f) ? a3 : 0.2f * a3;
    float p = a0 * gc2[lane] + a1 * gc2[lane + 32] + a2 * gc2[lane + 64] + a3 * gc2[lane + 96];
    #pragma unroll
    for (int o = 16; o; o >>= 1) p += __shfl_xor_sync(0xffffffffu, p, o);
    if (lane == 0) g_X2[b * Nn + n] = p;
}

__global__ void finalize_kernel(float* __restrict__ out, int E) {
    int idx = blockIdx.x * blockDim.x + threadIdx.x;
    if (idx >= Bsz * Nn) return;
    int b = idx / Nn, n = idx % Nn;
    int s = g_rowptr[b * (Nn + 1) + n];
    int t = g_rowptr[b * (Nn + 1) + n + 1];
    float acc = 0.f;
    for (int k = s; k < t; k++)
        acc += g_vals[b * E_MAX + k] * g_X2[b * Nn + g_cols[b * E_MAX + k]];
    out[idx] = 1.f / (1.f + expf(-acc));
}

// ---------------- launch ----------------
extern "C" void kernel_launch(void* const* d_in, const int* in_sizes, int n_in,
                              void* d_out, int out_size) {
    const float* search = (const float*)d_in[0];
    const float* xcorr  = (const float*)d_in[1];
    const int*   pairs  = (const int*)d_in[2];
    const float* phi_w1 = (const float*)d_in[3];
    const float* phi_b1 = (const float*)d_in[4];
    const float* gamma  = (const float*)d_in[5];
    const float* beta   = (const float*)d_in[6];
    const float* phi_w2 = (const float*)d_in[7];
    const float* phi_b2 = (const float*)d_in[8];
    const float* gc1_w  = (const float*)d_in[9];
    const float* gc2_w  = (const float*)d_in[10];
    float* out = (float*)d_out;

    int E = in_sizes[2] / (2 * Bsz);
    if (E > E_MAX) E = E_MAX;

    cudaFuncSetAttribute(phi_mma_kernel,
                         cudaFuncAttributeMaxDynamicSharedMemorySize, PHI_SMEM_BYTES);

    zero_kernel<<<(Bsz * Nn + 255) / 256, 256>>>();
    wsplit_kernel<<<(Cc * GC_HID + 255) / 256, 256>>>(phi_w1, gc1_w);
    transpose_kernel<<<dim3(Nn / 32, Cc / 32, Bsz), dim3(32, 32)>>>(search, xcorr);
    phi_mma_kernel<<<dim3((E + BLK_E - 1) / BLK_E, Bsz), 128, PHI_SMEM_BYTES>>>(pairs, phi_b1, E);
    edge_weight_kernel<<<dim3((E + 255) / 256, Bsz), 256>>>(gamma, beta, phi_w2, phi_b2, E);
    count_kernel<<<(Bsz * E + 255) / 256, 256>>>(pairs, E);
    scan_kernel<<<Bsz, 1024>>>(E);
    scatter_kernel<<<(Bsz * E + 255) / 256, 256>>>(pairs, E);
    x1_mma_kernel<<<dim3((Bsz * Nn) / 128, GC_HID / 64), 128>>>();
    spmm_kernel<<<dim3(Nn / 8, Bsz), 256>>>(gc2_w, E);
    finalize_kernel<<<(Bsz * Nn + 255) / 256, 256>>>(out, E);
}

// round 7
// speedup vs baseline: 2.0806x; 1.4524x over previous
#include <cuda_runtime.h>
#include <cuda_bf16.h>
#include <math.h>
#include <cstdint>

#define Bsz       16
#define Nn        1024
#define C_SEARCH  256
#define C_XCORR   64
#define Cc        320
#define PHI_H     64
#define GC_HID    128
#define E_MAX     10068
#define BN_EPS    1e-5f
#define BLK_E     128
#define NCHUNK    20          // Cc / 16
#define KCHUNK    16
#define SA_STR    20
#define SW_STR    72

// phi smem: W double buffer only, 4 planes * 66 uint4 per buffer
#define WBUF_F4   264
#define PHI_SMEM_BYTES  (2*WBUF_F4*16 + 192*4)      // 9216

// ---------------- scratch ----------------
__device__ __align__(16) float g_featT[Bsz * Nn * Cc];
__device__ uint4 g_w1P[NCHUNK * 256];        // bf16-packed W1 (k-permuted): [chunk][plane(4)][n(64)]
__device__ float g_gwhi[Cc * GC_HID];
__device__ float g_gwlo[Cc * GC_HID];
__device__ __align__(16) float g_h[Bsz * E_MAX * PHI_H];
__device__ float g_bn_sum[Bsz * PHI_H];
__device__ float g_bn_sumsq[Bsz * PHI_H];
__device__ float g_edgew[Bsz * E_MAX];
__device__ int   g_deg[Bsz * Nn];
__device__ int   g_rowptr[Bsz * (Nn + 1)];
__device__ int   g_cursor[Bsz * Nn];
__device__ int   g_cols[Bsz * E_MAX];
__device__ float g_vals[Bsz * E_MAX];
__device__ __align__(16) float g_X1[Bsz * Nn * GC_HID];
__device__ float g_X2[Bsz * Nn];

__device__ __forceinline__ float to_tf32(float x) {
    float y; asm("cvt.rna.tf32.f32 %0, %1;" : "=f"(y) : "f"(x)); return y;
}
__device__ __forceinline__ uint32_t fau(float x) { return __float_as_uint(x); }

// pack two floats into bf16x2 (lo half = first arg, hi half = second arg)
__device__ __forceinline__ uint32_t pack_bf(float lo, float hi) {
    uint32_t r;
    asm("cvt.rn.bf16x2.f32 %0, %1, %2;" : "=r"(r) : "f"(hi), "f"(lo));
    return r;
}
__device__ __forceinline__ float bf_round(float x) {
    return __bfloat162float(__float2bfloat16_rn(x));
}

__device__ __forceinline__ void mma_bf16(float* d, const uint32_t* a, const uint32_t* b) {
    asm volatile(
        "mma.sync.aligned.m16n8k16.row.col.f32.bf16.bf16.f32 "
        "{%0,%1,%2,%3}, {%4,%5,%6,%7}, {%8,%9}, {%0,%1,%2,%3};"
        : "+f"(d[0]), "+f"(d[1]), "+f"(d[2]), "+f"(d[3])
        : "r"(a[0]), "r"(a[1]), "r"(a[2]), "r"(a[3]), "r"(b[0]), "r"(b[1]));
}
__device__ __forceinline__ void mma_tf32(float* d, const uint32_t* a, const uint32_t* b) {
    asm volatile(
        "mma.sync.aligned.m16n8k8.row.col.f32.tf32.tf32.f32 "
        "{%0,%1,%2,%3}, {%4,%5,%6,%7}, {%8,%9}, {%0,%1,%2,%3};"
        : "+f"(d[0]), "+f"(d[1]), "+f"(d[2]), "+f"(d[3])
        : "r"(a[0]), "r"(a[1]), "r"(a[2]), "r"(a[3]), "r"(b[0]), "r"(b[1]));
}

__device__ __forceinline__ uint32_t smem_u32_of(const void* p) {
    uint32_t a;
    asm("{ .reg .u64 t; cvta.to.shared.u64 t, %1; cvt.u32.u64 %0, t; }" : "=r"(a) : "l"(p));
    return a;
}
__device__ __forceinline__ void cp_async16(uint32_t dst, const void* src) {
    asm volatile("cp.async.ca.shared.global [%0], [%1], 16;" :: "r"(dst), "l"(src));
}
#define CP_COMMIT() asm volatile("cp.async.commit_group;" ::: "memory")
#define CP_WAIT0()  asm volatile("cp.async.wait_group 0;" ::: "memory")

// ---------------- small kernels ----------------
__global__ void zero_kernel() {
    int i = blockIdx.x * blockDim.x + threadIdx.x;
    if (i < Bsz * Nn) g_deg[i] = 0;
    if (i < Bsz * PHI_H) { g_bn_sum[i] = 0.f; g_bn_sumsq[i] = 0.f; }
}

// pack W1 bf16 hi/lo planes (k-PERMUTED: fragment slots (2t,2t+1,2t+8,2t+9)
// hold physical k (4t,4t+1,4t+2,4t+3)) + split gc1_w (tf32)
__global__ void wsplit_kernel(const float* __restrict__ w1,
                              const float* __restrict__ gw) {
    int i = blockIdx.x * blockDim.x + threadIdx.x;
    if (i < NCHUNK * 256) {
        int c = i >> 8, rem = i & 255, t = rem >> 6, n = rem & 63;
        int kb = c * 16 + t * 4;
        float w0 = w1[(kb + 0) * 64 + n];
        float w1v= w1[(kb + 1) * 64 + n];
        float w2 = w1[(kb + 2) * 64 + n];
        float w3 = w1[(kb + 3) * 64 + n];
        float h0 = bf_round(w0), h1 = bf_round(w1v), h2 = bf_round(w2), h3 = bf_round(w3);
        uint4 o;
        o.x = pack_bf(h0, h1);
        o.y = pack_bf(h2, h3);
        o.z = pack_bf(w0 - h0, w1v - h1);
        o.w = pack_bf(w2 - h2, w3 - h3);
        g_w1P[i] = o;
    }
    if (i < Cc * GC_HID) {
        float v = gw[i];
        float hi = to_tf32(v);
        g_gwhi[i] = hi;
        g_gwlo[i] = to_tf32(v - hi);
    }
}

__global__ void transpose_kernel(const float* __restrict__ search,
                                 const float* __restrict__ xcorr) {
    __shared__ float tile[32][33];
    int b  = blockIdx.z;
    int c0 = blockIdx.y * 32;
    int n0 = blockIdx.x * 32;
    int tx = threadIdx.x, ty = threadIdx.y;
    int c = c0 + ty, n = n0 + tx;
    float v;
    if (c < C_SEARCH) v = search[((size_t)b * C_SEARCH + c) * Nn + n];
    else              v = xcorr[((size_t)b * C_XCORR + (c - C_SEARCH)) * Nn + n];
    tile[ty][tx] = v;
    __syncthreads();
    g_featT[((size_t)b * Nn + n0 + ty) * Cc + c0 + tx] = tile[tx][ty];
}

// ---------------- K1: phi GEMM, bf16 split, quad-cooperative gather, A in regs ----
// 128 threads = 4 warps; block tile 128 edges x 64 cols; warp tile 32x64.
// Lane (gid,tig) loads float4 #tig of rows warp*32 + rblk*8 + gid (coalesced per quad);
// with the k-permutation these ARE the A fragments. No A smem.
__global__ __launch_bounds__(128) void phi_mma_kernel(
        const int* __restrict__ pairs, const float* __restrict__ b1, int E) {
    extern __shared__ uint4 smem4[];
    uint4* sW = smem4;                  // [2][264]
    float* sBias = (float*)(smem4 + 2 * WBUF_F4);
    float* sSum  = sBias + 64;
    float* sSq   = sBias + 128;

    int tid = threadIdx.x, warp = tid >> 5, lane = tid & 31;
    int gid = lane >> 2, tig = lane & 3;
    int b = blockIdx.y, e0 = blockIdx.x * BLK_E;

    if (tid < 64) { sBias[tid] = b1[tid]; sSum[tid] = 0.f; sSq[tid] = 0.f; }

    const float* fb = g_featT + (size_t)b * Nn * Cc;
    const float4* rx[4];
    const float4* ry[4];
    #pragma unroll
    for (int r = 0; r < 4; r++) {
        int e = e0 + warp * 32 + r * 8 + gid;
        int2 p = (e < E) ? ((const int2*)pairs)[(size_t)b * E + e] : make_int2(0, 0);
        rx[r] = (const float4*)(fb + (size_t)p.x * Cc);
        ry[r] = (const float4*)(fb + (size_t)p.y * Cc);
    }

    uint32_t smem_base = smem_u32_of(smem4);
    float4 gx[4], gy[4];
    float acc[2][8][4] = {};

    // ---- prologue: W chunk 0 + gather chunk 0 ----
    {
        const uint4* src = g_w1P;
        #pragma unroll
        for (int i = 0; i < 2; i++) {
            int idx = tid + i * 128, pl = idx >> 6, n = idx & 63;
            cp_async16(smem_base + (uint32_t)(pl * 66 + n) * 16u, src + idx);
        }
        CP_COMMIT();
        #pragma unroll
        for (int r = 0; r < 4; r++) { gx[r] = rx[r][tig]; gy[r] = ry[r][tig]; }
        CP_WAIT0();
    }
    __syncthreads();

    // ---- main loop ----
    for (int c = 0; c < NCHUNK; c++) {
        int cur = c & 1, nxt = cur ^ 1;
        bool more = (c + 1 < NCHUNK);

        // build A fragments for chunk c from registers
        uint4 fr[4];
        #pragma unroll
        for (int r = 0; r < 4; r++) {
            float d0 = fabsf(gx[r].x - gy[r].x);
            float d1 = fabsf(gx[r].y - gy[r].y);
            float d2 = fabsf(gx[r].z - gy[r].z);
            float d3 = fabsf(gx[r].w - gy[r].w);
            float h0 = bf_round(d0), h1 = bf_round(d1);
            float h2 = bf_round(d2), h3 = bf_round(d3);
            fr[r].x = pack_bf(h0, h1);
            fr[r].y = pack_bf(h2, h3);
            fr[r].z = pack_bf(d0 - h0, d1 - h1);
            fr[r].w = pack_bf(d2 - h2, d3 - h3);
        }

        // prefetch chunk c+1 (W via cp.async, A via quad-coalesced LDG)
        if (more) {
            const uint4* src = g_w1P + (c + 1) * 256;
            #pragma unroll
            for (int i = 0; i < 2; i++) {
                int idx = tid + i * 128, pl = idx >> 6, n = idx & 63;
                cp_async16(smem_base + (uint32_t)(nxt * WBUF_F4 + pl * 66 + n) * 16u, src + idx);
            }
            CP_COMMIT();
            int o = (c + 1) * 4 + tig;
            #pragma unroll
            for (int r = 0; r < 4; r++) { gx[r] = rx[r][o]; gy[r] = ry[r][o]; }
        }

        // MMA on chunk c
        uint4 bfr[8];
        #pragma unroll
        for (int nt = 0; nt < 8; nt++)
            bfr[nt] = sW[cur * WBUF_F4 + tig * 66 + nt * 8 + gid];
        #pragma unroll
        for (int mt = 0; mt < 2; mt++) {
            uint32_t ah[4] = { fr[2*mt].x, fr[2*mt+1].x, fr[2*mt].y, fr[2*mt+1].y };
            uint32_t al[4] = { fr[2*mt].z, fr[2*mt+1].z, fr[2*mt].w, fr[2*mt+1].w };
            #pragma unroll
            for (int nt = 0; nt < 8; nt++) {
                uint32_t bh[2] = { bfr[nt].x, bfr[nt].y };
                uint32_t bl[2] = { bfr[nt].z, bfr[nt].w };
                mma_bf16(acc[mt][nt], ah, bh);
                mma_bf16(acc[mt][nt], ah, bl);
                mma_bf16(acc[mt][nt], al, bh);
            }
        }
        if (more) CP_WAIT0();
        __syncthreads();
    }

    // ---- epilogue: bias, store h, BN partial sums ----
    float ts[8][2] = {}, tq[8][2] = {};
    #pragma unroll
    for (int mt = 0; mt < 2; mt++) {
        #pragma unroll
        for (int rh = 0; rh < 2; rh++) {
            int el = warp * 32 + mt * 16 + rh * 8 + gid;
            int e2 = e0 + el;
            bool valid = (e2 < E);
            float* dst = g_h + (((size_t)b * E_MAX) + e2) * PHI_H;
            #pragma unroll
            for (int nt = 0; nt < 8; nt++) {
                int col = nt * 8 + tig * 2;
                float v0 = acc[mt][nt][rh * 2 + 0] + sBias[col];
                float v1 = acc[mt][nt][rh * 2 + 1] + sBias[col + 1];
                if (valid) {
                    *(float2*)(dst + col) = make_float2(v0, v1);
                    ts[nt][0] += v0; tq[nt][0] += v0 * v0;
                    ts[nt][1] += v1; tq[nt][1] += v1 * v1;
                }
            }
        }
    }
    #pragma unroll
    for (int nt = 0; nt < 8; nt++) {
        #pragma unroll
        for (int j = 0; j < 2; j++) {
            float s = ts[nt][j], q = tq[nt][j];
            #pragma unroll
            for (int o = 4; o < 32; o <<= 1) {
                s += __shfl_xor_sync(0xffffffffu, s, o);
                q += __shfl_xor_sync(0xffffffffu, q, o);
            }
            if (gid == 0) {
                int col = nt * 8 + tig * 2 + j;
                atomicAdd(&sSum[col], s);
                atomicAdd(&sSq[col], q);
            }
        }
    }
    __syncthreads();
    if (tid < 64) {
        atomicAdd(&g_bn_sum[b * PHI_H + tid], sSum[tid]);
        atomicAdd(&g_bn_sumsq[b * PHI_H + tid], sSq[tid]);
    }
}

// ---------------- K2: BN + ReLU + Linear + sigmoid ----------------
__global__ __launch_bounds__(256) void edge_weight_kernel(
        const float* __restrict__ gamma, const float* __restrict__ beta,
        const float* __restrict__ w2, const float* __restrict__ b2, int E) {
    int b = blockIdx.y;
    __shared__ __align__(16) float sa[64], sc[64], sw2[64];
    int tid = threadIdx.x;
    if (tid < 64) {
        float mu  = g_bn_sum[b * PHI_H + tid] / (float)E;
        float var = g_bn_sumsq[b * PHI_H + tid] / (float)E - mu * mu;
        var = fmaxf(var, 0.f);
        float inv = rsqrtf(var + BN_EPS);
        float a = gamma[tid] * inv;
        sa[tid] = a;
        sc[tid] = beta[tid] - mu * a;
        sw2[tid] = w2[tid];
    }
    __syncthreads();
    int warp = tid >> 5, lane = tid & 31;
    int sub = lane >> 4, l16 = lane & 15;
    float4 A = *(float4*)&sa[l16 * 4];
    float4 C = *(float4*)&sc[l16 * 4];
    float4 W = *(float4*)&sw2[l16 * 4];
    float bb = b2[0];
    int base = blockIdx.x * 256 + warp * 32;
    #pragma unroll 4
    for (int it = 0; it < 16; it++) {
        int e = base + it * 2 + sub;
        if (e >= E) continue;
        float4 h4 = *(const float4*)(g_h + (((size_t)b * E_MAX) + e) * PHI_H + l16 * 4);
        float p = fmaxf(A.x * h4.x + C.x, 0.f) * W.x
                + fmaxf(A.y * h4.y + C.y, 0.f) * W.y
                + fmaxf(A.z * h4.z + C.z, 0.f) * W.z
                + fmaxf(A.w * h4.w + C.w, 0.f) * W.w;
        #pragma unroll
        for (int o = 8; o; o >>= 1) p += __shfl_xor_sync(0xffffffffu, p, o);
        if (l16 == 0) {
            float z = p + bb;
            g_edgew[b * E_MAX + e] = 1.f / (1.f + expf(-z));
        }
    }
}

// ---------------- CSR build ----------------
__global__ void count_kernel(const int* __restrict__ pairs, int E) {
    int idx = blockIdx.x * blockDim.x + threadIdx.x;
    if (idx >= Bsz * E) return;
    int b = idx / E, e = idx % E;
    atomicAdd(&g_deg[b * Nn + pairs[((size_t)b * E + e) * 2]], 1);
}

__global__ __launch_bounds__(1024) void scan_kernel(int E) {
    int b = blockIdx.x, tid = threadIdx.x;
    int v = g_deg[b * Nn + tid];
    int x = v;
    #pragma unroll
    for (int o = 1; o < 32; o <<= 1) {
        int y = __shfl_up_sync(0xffffffffu, x, o);
        if ((tid & 31) >= o) x += y;
    }
    __shared__ int wsum[32];
    if ((tid & 31) == 31) wsum[tid >> 5] = x;
    __syncthreads();
    if (tid < 32) {
        int y = wsum[tid];
        #pragma unroll
        for (int o = 1; o < 32; o <<= 1) {
            int z = __shfl_up_sync(0xffffffffu, y, o);
            if (tid >= o) y += z;
        }
        wsum[tid] = y;
    }
    __syncthreads();
    int incl = x + ((tid >= 32) ? wsum[(tid >> 5) - 1] : 0);
    int excl = incl - v;
    g_rowptr[b * (Nn + 1) + tid] = excl;
    g_cursor[b * Nn + tid] = excl;
    if (tid == Nn - 1) g_rowptr[b * (Nn + 1) + Nn] = incl;
}

__global__ void scatter_kernel(const int* __restrict__ pairs, int E) {
    int idx = blockIdx.x * blockDim.x + threadIdx.x;
    if (idx >= Bsz * E) return;
    int b = idx / E, e = idx % E;
    int p0 = pairs[((size_t)b * E + e) * 2 + 0];
    int p1 = pairs[((size_t)b * E + e) * 2 + 1];
    int pos = atomicAdd(&g_cursor[b * Nn + p0], 1);
    g_cols[b * E_MAX + pos] = p1;
    g_vals[b * E_MAX + pos] = g_edgew[b * E_MAX + e];
}

// ---------------- K4: X1 = featT @ gc1_w via 3xTF32 ----------------
__global__ __launch_bounds__(128) void x1_mma_kernel() {
    __shared__ float sAh[128 * SA_STR];
    __shared__ float sAl[128 * SA_STR];
    __shared__ float sWh[KCHUNK * SW_STR];
    __shared__ float sWl[KCHUNK * SW_STR];

    int tid = threadIdx.x, warp = tid >> 5, lane = tid & 31;
    int gid = lane >> 2, tig = lane & 3;
    int m0 = blockIdx.x * 128;
    int n0 = blockIdx.y * 64;

    float acc[2][8][4] = {};

    for (int kc = 0; kc < Cc; kc += KCHUNK) {
        __syncthreads();
        #pragma unroll
        for (int i = 0; i < 4; i++) {
            int idx = tid + i * 128;
            int row = idx >> 2, c4 = idx & 3;
            float4 a = *(const float4*)(g_featT + (size_t)(m0 + row) * Cc + kc + c4 * 4);
            float4 ah4, al4;
            ah4.x = to_tf32(a.x); al4.x = to_tf32(a.x - ah4.x);
            ah4.y = to_tf32(a.y); al4.y = to_tf32(a.y - ah4.y);
            ah4.z = to_tf32(a.z); al4.z = to_tf32(a.z - ah4.z);
            ah4.w = to_tf32(a.w); al4.w = to_tf32(a.w - ah4.w);
            *(float4*)&sAh[row * SA_STR + c4 * 4] = ah4;
            *(float4*)&sAl[row * SA_STR + c4 * 4] = al4;
        }
        #pragma unroll
        for (int i = 0; i < 2; i++) {
            int idx = tid + i * 128;
            int row = idx >> 4, c4 = idx & 15;
            float4 wh = *(const float4*)(g_gwhi + (size_t)(kc + row) * GC_HID + n0 + c4 * 4);
            float4 wl = *(const float4*)(g_gwlo + (size_t)(kc + row) * GC_HID + n0 + c4 * 4);
            *(float4*)&sWh[row * SW_STR + c4 * 4] = wh;
            *(float4*)&sWl[row * SW_STR + c4 * 4] = wl;
        }
        __syncthreads();

        #pragma unroll
        for (int ks = 0; ks < 2; ks++) {
            int k0 = ks * 8;
            uint32_t bh[8][2], bl[8][2];
            #pragma unroll
            for (int nt = 0; nt < 8; nt++) {
                int c = nt * 8 + gid;
                bh[nt][0] = fau(sWh[(k0 + tig)     * SW_STR + c]);
                bh[nt][1] = fau(sWh[(k0 + tig + 4) * SW_STR + c]);
                bl[nt][0] = fau(sWl[(k0 + tig)     * SW_STR + c]);
                bl[nt][1] = fau(sWl[(k0 + tig + 4) * SW_STR + c]);
            }
            #pragma unroll
            for (int mt = 0; mt < 2; mt++) {
                int r = warp * 32 + mt * 16 + gid;
                uint32_t ah[4], al[4];
                ah[0] = fau(sAh[r       * SA_STR + k0 + tig]);
                ah[1] = fau(sAh[(r + 8) * SA_STR + k0 + tig]);
                ah[2] = fau(sAh[r       * SA_STR + k0 + tig + 4]);
                ah[3] = fau(sAh[(r + 8) * SA_STR + k0 + tig + 4]);
                al[0] = fau(sAl[r       * SA_STR + k0 + tig]);
                al[1] = fau(sAl[(r + 8) * SA_STR + k0 + tig]);
                al[2] = fau(sAl[r       * SA_STR + k0 + tig + 4]);
                al[3] = fau(sAl[(r + 8) * SA_STR + k0 + tig + 4]);
                #pragma unroll
                for (int nt = 0; nt < 8; nt++) {
                    mma_tf32(acc[mt][nt], ah, bh[nt]);
                    mma_tf32(acc[mt][nt], ah, bl[nt]);
                    mma_tf32(acc[mt][nt], al, bh[nt]);
                }
            }
        }
    }

    #pragma unroll
    for (int mt = 0; mt < 2; mt++) {
        #pragma unroll
        for (int rh = 0; rh < 2; rh++) {
            int m = m0 + warp * 32 + mt * 16 + rh * 8 + gid;
            float* dst = g_X1 + (size_t)m * GC_HID + n0;
            #pragma unroll
            for (int nt = 0; nt < 8; nt++) {
                int col = nt * 8 + tig * 2;
                *(float2*)(dst + col) =
                    make_float2(acc[mt][nt][rh * 2 + 0], acc[mt][nt][rh * 2 + 1]);
            }
        }
    }
}

// ---------------- K5: SpMM + leaky + fused gc2 dot ----------------
__global__ __launch_bounds__(256) void spmm_kernel(const float* __restrict__ gc2, int E) {
    int warp = threadIdx.x >> 5, lane = threadIdx.x & 31;
    int n = blockIdx.x * 8 + warp;
    int b = blockIdx.y;
    int s = g_rowptr[b * (Nn + 1) + n];
    int t = g_rowptr[b * (Nn + 1) + n + 1];
    float a0 = 0, a1 = 0, a2 = 0, a3 = 0;
    const float* Xb = g_X1 + (size_t)b * Nn * GC_HID;
    for (int k = s; k < t; k++) {
        float w = g_vals[b * E_MAX + k];
        int   c = g_cols[b * E_MAX + k];
        const float* xr = Xb + (size_t)c * GC_HID + lane;
        a0 += w * xr[0];
        a1 += w * xr[32];
        a2 += w * xr[64];
        a3 += w * xr[96];
    }
    a0 = (a0 > 0.f) ? a0 : 0.2f * a0;
    a1 = (a1 > 0.f) ? a1 : 0.2f * a1;
    a2 = (a2 > 0.f) ? a2 : 0.2f * a2;
    a3 = (a3 > 0.f) ? a3 : 0.2f * a3;
    float p = a0 * gc2[lane] + a1 * gc2[lane + 32] + a2 * gc2[lane + 64] + a3 * gc2[lane + 96];
    #pragma unroll
    for (int o = 16; o; o >>= 1) p += __shfl_xor_sync(0xffffffffu, p, o);
    if (lane == 0) g_X2[b * Nn + n] = p;
}

__global__ void finalize_kernel(float* __restrict__ out, int E) {
    int idx = blockIdx.x * blockDim.x + threadIdx.x;
    if (idx >= Bsz * Nn) return;
    int b = idx / Nn, n = idx % Nn;
    int s = g_rowptr[b * (Nn + 1) + n];
    int t = g_rowptr[b * (Nn + 1) + n + 1];
    float acc = 0.f;
    for (int k = s; k < t; k++)
        acc += g_vals[b * E_MAX + k] * g_X2[b * Nn + g_cols[b * E_MAX + k]];
    out[idx] = 1.f / (1.f + expf(-acc));
}

// ---------------- launch ----------------
extern "C" void kernel_launch(void* const* d_in, const int* in_sizes, int n_in,
                              void* d_out, int out_size) {
    const float* search = (const float*)d_in[0];
    const float* xcorr  = (const float*)d_in[1];
    const int*   pairs  = (const int*)d_in[2];
    const float* phi_w1 = (const float*)d_in[3];
    const float* phi_b1 = (const float*)d_in[4];
    const float* gamma  = (const float*)d_in[5];
    const float* beta   = (const float*)d_in[6];
    const float* phi_w2 = (const float*)d_in[7];
    const float* phi_b2 = (const float*)d_in[8];
    const float* gc1_w  = (const float*)d_in[9];
    const float* gc2_w  = (const float*)d_in[10];
    float* out = (float*)d_out;

    int E = in_sizes[2] / (2 * Bsz);
    if (E > E_MAX) E = E_MAX;

    cudaFuncSetAttribute(phi_mma_kernel,
                         cudaFuncAttributeMaxDynamicSharedMemorySize, PHI_SMEM_BYTES);

    zero_kernel<<<(Bsz * Nn + 255) / 256, 256>>>();
    wsplit_kernel<<<(Cc * GC_HID + 255) / 256, 256>>>(phi_w1, gc1_w);
    transpose_kernel<<<dim3(Nn / 32, Cc / 32, Bsz), dim3(32, 32)>>>(search, xcorr);
    phi_mma_kernel<<<dim3((E + BLK_E - 1) / BLK_E, Bsz), 128, PHI_SMEM_BYTES>>>(pairs, phi_b1, E);
    edge_weight_kernel<<<dim3((E + 255) / 256, Bsz), 256>>>(gamma, beta, phi_w2, phi_b2, E);
    count_kernel<<<(Bsz * E + 255) / 256, 256>>>(pairs, E);
    scan_kernel<<<Bsz, 1024>>>(E);
    scatter_kernel<<<(Bsz * E + 255) / 256, 256>>>(pairs, E);
    x1_mma_kernel<<<dim3((Bsz * Nn) / 128, GC_HID / 64), 128>>>();
    spmm_kernel<<<dim3(Nn / 8, Bsz), 256>>>(gc2_w, E);
    finalize_kernel<<<(Bsz * Nn + 255) / 256, 256>>>(out, E);
}

// round 8
// speedup vs baseline: 2.3300x; 1.1199x over previous
#include <cuda_runtime.h>
#include <cuda_bf16.h>
#include <math.h>
#include <cstdint>

#define Bsz       16
#define Nn        1024
#define C_SEARCH  256
#define C_XCORR   64
#define Cc        320
#define PHI_H     64
#define GC_HID    128
#define E_MAX     10068
#define BN_EPS    1e-5f
#define BLK_E     128
#define NCHUNK    20          // Cc / 16

// W double buffer: 4 planes * 66 uint4 per buffer
#define WBUF_F4   264
#define PHI_SMEM_BYTES  (2*WBUF_F4*16 + 192*4)      // 9216

// ---------------- scratch ----------------
__device__ __align__(16) float g_featT[Bsz * Nn * Cc];
__device__ uint4 g_w1P[NCHUNK * 256];        // bf16-packed W1 (k-permuted): [chunk][plane(4)][n(64)]
__device__ uint4 g_gwP[NCHUNK * 512];        // bf16-packed gc1_w (k-permuted): [chunk][plane(4)][n(128)]
__device__ __align__(16) float g_h[Bsz * E_MAX * PHI_H];
__device__ float g_bn_sum[Bsz * PHI_H];
__device__ float g_bn_sumsq[Bsz * PHI_H];
__device__ float g_edgew[Bsz * E_MAX];
__device__ int   g_deg[Bsz * Nn];
__device__ int   g_rowptr[Bsz * (Nn + 1)];
__device__ int   g_cursor[Bsz * Nn];
__device__ int   g_cols[Bsz * E_MAX];
__device__ float g_vals[Bsz * E_MAX];
__device__ __align__(16) float g_X1[Bsz * Nn * GC_HID];
__device__ float g_X2[Bsz * Nn];

__device__ __forceinline__ uint32_t pack_bf(float lo, float hi) {
    uint32_t r;
    asm("cvt.rn.bf16x2.f32 %0, %1, %2;" : "=r"(r) : "f"(hi), "f"(lo));
    return r;
}
__device__ __forceinline__ float bf_round(float x) {
    return __bfloat162float(__float2bfloat16_rn(x));
}

__device__ __forceinline__ void mma_bf16(float* d, const uint32_t* a, const uint32_t* b) {
    asm volatile(
        "mma.sync.aligned.m16n8k16.row.col.f32.bf16.bf16.f32 "
        "{%0,%1,%2,%3}, {%4,%5,%6,%7}, {%8,%9}, {%0,%1,%2,%3};"
        : "+f"(d[0]), "+f"(d[1]), "+f"(d[2]), "+f"(d[3])
        : "r"(a[0]), "r"(a[1]), "r"(a[2]), "r"(a[3]), "r"(b[0]), "r"(b[1]));
}

__device__ __forceinline__ uint32_t smem_u32_of(const void* p) {
    uint32_t a;
    asm("{ .reg .u64 t; cvta.to.shared.u64 t, %1; cvt.u32.u64 %0, t; }" : "=r"(a) : "l"(p));
    return a;
}
__device__ __forceinline__ void cp_async16(uint32_t dst, const void* src) {
    asm volatile("cp.async.ca.shared.global [%0], [%1], 16;" :: "r"(dst), "l"(src));
}
#define CP_COMMIT() asm volatile("cp.async.commit_group;" ::: "memory")
#define CP_WAIT0()  asm volatile("cp.async.wait_group 0;" ::: "memory")

// ---------------- K0: prep = zero + pack W1 + pack gc1 ----------------
__global__ void prep_kernel(const float* __restrict__ w1,
                            const float* __restrict__ gw) {
    int i = blockIdx.x * blockDim.x + threadIdx.x;
    if (i < Bsz * Nn) g_deg[i] = 0;
    if (i < Bsz * PHI_H) { g_bn_sum[i] = 0.f; g_bn_sumsq[i] = 0.f; }
    if (i < NCHUNK * 256) {                       // W1: [chunk][t(4)][n(64)]
        int c = i >> 8, rem = i & 255, t = rem >> 6, n = rem & 63;
        int kb = c * 16 + t * 4;
        float w0 = w1[(kb + 0) * 64 + n];
        float w1v= w1[(kb + 1) * 64 + n];
        float w2 = w1[(kb + 2) * 64 + n];
        float w3 = w1[(kb + 3) * 64 + n];
        float h0 = bf_round(w0), h1 = bf_round(w1v), h2 = bf_round(w2), h3 = bf_round(w3);
        uint4 o;
        o.x = pack_bf(h0, h1);
        o.y = pack_bf(h2, h3);
        o.z = pack_bf(w0 - h0, w1v - h1);
        o.w = pack_bf(w2 - h2, w3 - h3);
        g_w1P[i] = o;
    }
    if (i < NCHUNK * 512) {                       // gc1: [chunk][t(4)][n(128)]
        int c = i >> 9, rem = i & 511, t = rem >> 7, n = rem & 127;
        int kb = c * 16 + t * 4;
        float w0 = gw[(kb + 0) * GC_HID + n];
        float w1v= gw[(kb + 1) * GC_HID + n];
        float w2 = gw[(kb + 2) * GC_HID + n];
        float w3 = gw[(kb + 3) * GC_HID + n];
        float h0 = bf_round(w0), h1 = bf_round(w1v), h2 = bf_round(w2), h3 = bf_round(w3);
        uint4 o;
        o.x = pack_bf(h0, h1);
        o.y = pack_bf(h2, h3);
        o.z = pack_bf(w0 - h0, w1v - h1);
        o.w = pack_bf(w2 - h2, w3 - h3);
        g_gwP[i] = o;
    }
}

__global__ void transpose_kernel(const float* __restrict__ search,
                                 const float* __restrict__ xcorr) {
    __shared__ float tile[32][33];
    int b  = blockIdx.z;
    int c0 = blockIdx.y * 32;
    int n0 = blockIdx.x * 32;
    int tx = threadIdx.x, ty = threadIdx.y;
    int c = c0 + ty, n = n0 + tx;
    float v;
    if (c < C_SEARCH) v = search[((size_t)b * C_SEARCH + c) * Nn + n];
    else              v = xcorr[((size_t)b * C_XCORR + (c - C_SEARCH)) * Nn + n];
    tile[ty][tx] = v;
    __syncthreads();
    g_featT[((size_t)b * Nn + n0 + ty) * Cc + c0 + tx] = tile[tx][ty];
}

// ---------------- K1: phi GEMM (unchanged from R7 winner) ----------------
__global__ __launch_bounds__(128) void phi_mma_kernel(
        const int* __restrict__ pairs, const float* __restrict__ b1, int E) {
    extern __shared__ uint4 smem4[];
    uint4* sW = smem4;                  // [2][264]
    float* sBias = (float*)(smem4 + 2 * WBUF_F4);
    float* sSum  = sBias + 64;
    float* sSq   = sBias + 128;

    int tid = threadIdx.x, warp = tid >> 5, lane = tid & 31;
    int gid = lane >> 2, tig = lane & 3;
    int b = blockIdx.y, e0 = blockIdx.x * BLK_E;

    if (tid < 64) { sBias[tid] = b1[tid]; sSum[tid] = 0.f; sSq[tid] = 0.f; }

    const float* fb = g_featT + (size_t)b * Nn * Cc;
    const float4* rx[4];
    const float4* ry[4];
    #pragma unroll
    for (int r = 0; r < 4; r++) {
        int e = e0 + warp * 32 + r * 8 + gid;
        int2 p = (e < E) ? ((const int2*)pairs)[(size_t)b * E + e] : make_int2(0, 0);
        rx[r] = (const float4*)(fb + (size_t)p.x * Cc);
        ry[r] = (const float4*)(fb + (size_t)p.y * Cc);
    }

    uint32_t smem_base = smem_u32_of(smem4);
    float4 gx[4], gy[4];
    float acc[2][8][4] = {};

    {
        const uint4* src = g_w1P;
        #pragma unroll
        for (int i = 0; i < 2; i++) {
            int idx = tid + i * 128, pl = idx >> 6, n = idx & 63;
            cp_async16(smem_base + (uint32_t)(pl * 66 + n) * 16u, src + idx);
        }
        CP_COMMIT();
        #pragma unroll
        for (int r = 0; r < 4; r++) { gx[r] = rx[r][tig]; gy[r] = ry[r][tig]; }
        CP_WAIT0();
    }
    __syncthreads();

    for (int c = 0; c < NCHUNK; c++) {
        int cur = c & 1, nxt = cur ^ 1;
        bool more = (c + 1 < NCHUNK);

        uint4 fr[4];
        #pragma unroll
        for (int r = 0; r < 4; r++) {
            float d0 = fabsf(gx[r].x - gy[r].x);
            float d1 = fabsf(gx[r].y - gy[r].y);
            float d2 = fabsf(gx[r].z - gy[r].z);
            float d3 = fabsf(gx[r].w - gy[r].w);
            float h0 = bf_round(d0), h1 = bf_round(d1);
            float h2 = bf_round(d2), h3 = bf_round(d3);
            fr[r].x = pack_bf(h0, h1);
            fr[r].y = pack_bf(h2, h3);
            fr[r].z = pack_bf(d0 - h0, d1 - h1);
            fr[r].w = pack_bf(d2 - h2, d3 - h3);
        }

        if (more) {
            const uint4* src = g_w1P + (c + 1) * 256;
            #pragma unroll
            for (int i = 0; i < 2; i++) {
                int idx = tid + i * 128, pl = idx >> 6, n = idx & 63;
                cp_async16(smem_base + (uint32_t)(nxt * WBUF_F4 + pl * 66 + n) * 16u, src + idx);
            }
            CP_COMMIT();
            int o = (c + 1) * 4 + tig;
            #pragma unroll
            for (int r = 0; r < 4; r++) { gx[r] = rx[r][o]; gy[r] = ry[r][o]; }
        }

        uint4 bfr[8];
        #pragma unroll
        for (int nt = 0; nt < 8; nt++)
            bfr[nt] = sW[cur * WBUF_F4 + tig * 66 + nt * 8 + gid];
        #pragma unroll
        for (int mt = 0; mt < 2; mt++) {
            uint32_t ah[4] = { fr[2*mt].x, fr[2*mt+1].x, fr[2*mt].y, fr[2*mt+1].y };
            uint32_t al[4] = { fr[2*mt].z, fr[2*mt+1].z, fr[2*mt].w, fr[2*mt+1].w };
            #pragma unroll
            for (int nt = 0; nt < 8; nt++) {
                uint32_t bh[2] = { bfr[nt].x, bfr[nt].y };
                uint32_t bl[2] = { bfr[nt].z, bfr[nt].w };
                mma_bf16(acc[mt][nt], ah, bh);
                mma_bf16(acc[mt][nt], ah, bl);
                mma_bf16(acc[mt][nt], al, bh);
            }
        }
        if (more) CP_WAIT0();
        __syncthreads();
    }

    float ts[8][2] = {}, tq[8][2] = {};
    #pragma unroll
    for (int mt = 0; mt < 2; mt++) {
        #pragma unroll
        for (int rh = 0; rh < 2; rh++) {
            int el = warp * 32 + mt * 16 + rh * 8 + gid;
            int e2 = e0 + el;
            bool valid = (e2 < E);
            float* dst = g_h + (((size_t)b * E_MAX) + e2) * PHI_H;
            #pragma unroll
            for (int nt = 0; nt < 8; nt++) {
                int col = nt * 8 + tig * 2;
                float v0 = acc[mt][nt][rh * 2 + 0] + sBias[col];
                float v1 = acc[mt][nt][rh * 2 + 1] + sBias[col + 1];
                if (valid) {
                    *(float2*)(dst + col) = make_float2(v0, v1);
                    ts[nt][0] += v0; tq[nt][0] += v0 * v0;
                    ts[nt][1] += v1; tq[nt][1] += v1 * v1;
                }
            }
        }
    }
    #pragma unroll
    for (int nt = 0; nt < 8; nt++) {
        #pragma unroll
        for (int j = 0; j < 2; j++) {
            float s = ts[nt][j], q = tq[nt][j];
            #pragma unroll
            for (int o = 4; o < 32; o <<= 1) {
                s += __shfl_xor_sync(0xffffffffu, s, o);
                q += __shfl_xor_sync(0xffffffffu, q, o);
            }
            if (gid == 0) {
                int col = nt * 8 + tig * 2 + j;
                atomicAdd(&sSum[col], s);
                atomicAdd(&sSq[col], q);
            }
        }
    }
    __syncthreads();
    if (tid < 64) {
        atomicAdd(&g_bn_sum[b * PHI_H + tid], sSum[tid]);
        atomicAdd(&g_bn_sumsq[b * PHI_H + tid], sSq[tid]);
    }
}

// ---------------- K2: BN + ReLU + Linear + sigmoid (+ degree count) ----------------
__global__ __launch_bounds__(256) void edge_weight_kernel(
        const int* __restrict__ pairs,
        const float* __restrict__ gamma, const float* __restrict__ beta,
        const float* __restrict__ w2, const float* __restrict__ b2, int E) {
    int b = blockIdx.y;
    __shared__ __align__(16) float sa[64], sc[64], sw2[64];
    int tid = threadIdx.x;
    if (tid < 64) {
        float mu  = g_bn_sum[b * PHI_H + tid] / (float)E;
        float var = g_bn_sumsq[b * PHI_H + tid] / (float)E - mu * mu;
        var = fmaxf(var, 0.f);
        float inv = rsqrtf(var + BN_EPS);
        float a = gamma[tid] * inv;
        sa[tid] = a;
        sc[tid] = beta[tid] - mu * a;
        sw2[tid] = w2[tid];
    }
    __syncthreads();
    int warp = tid >> 5, lane = tid & 31;
    int sub = lane >> 4, l16 = lane & 15;
    float4 A = *(float4*)&sa[l16 * 4];
    float4 C = *(float4*)&sc[l16 * 4];
    float4 W = *(float4*)&sw2[l16 * 4];
    float bb = b2[0];
    int base = blockIdx.x * 256 + warp * 32;
    #pragma unroll 4
    for (int it = 0; it < 16; it++) {
        int e = base + it * 2 + sub;
        if (e >= E) continue;
        float4 h4 = *(const float4*)(g_h + (((size_t)b * E_MAX) + e) * PHI_H + l16 * 4);
        float p = fmaxf(A.x * h4.x + C.x, 0.f) * W.x
                + fmaxf(A.y * h4.y + C.y, 0.f) * W.y
                + fmaxf(A.z * h4.z + C.z, 0.f) * W.z
                + fmaxf(A.w * h4.w + C.w, 0.f) * W.w;
        #pragma unroll
        for (int o = 8; o; o >>= 1) p += __shfl_xor_sync(0xffffffffu, p, o);
        if (l16 == 0) {
            float z = p + bb;
            g_edgew[b * E_MAX + e] = 1.f / (1.f + expf(-z));
            int p0 = pairs[((size_t)b * E + e) * 2];
            atomicAdd(&g_deg[b * Nn + p0], 1);          // fused count
        }
    }
}

// ---------------- CSR build ----------------
__global__ __launch_bounds__(1024) void scan_kernel(int E) {
    int b = blockIdx.x, tid = threadIdx.x;
    int v = g_deg[b * Nn + tid];
    int x = v;
    #pragma unroll
    for (int o = 1; o < 32; o <<= 1) {
        int y = __shfl_up_sync(0xffffffffu, x, o);
        if ((tid & 31) >= o) x += y;
    }
    __shared__ int wsum[32];
    if ((tid & 31) == 31) wsum[tid >> 5] = x;
    __syncthreads();
    if (tid < 32) {
        int y = wsum[tid];
        #pragma unroll
        for (int o = 1; o < 32; o <<= 1) {
            int z = __shfl_up_sync(0xffffffffu, y, o);
            if (tid >= o) y += z;
        }
        wsum[tid] = y;
    }
    __syncthreads();
    int incl = x + ((tid >= 32) ? wsum[(tid >> 5) - 1] : 0);
    int excl = incl - v;
    g_rowptr[b * (Nn + 1) + tid] = excl;
    g_cursor[b * Nn + tid] = excl;
    if (tid == Nn - 1) g_rowptr[b * (Nn + 1) + Nn] = incl;
}

__global__ void scatter_kernel(const int* __restrict__ pairs, int E) {
    int idx = blockIdx.x * blockDim.x + threadIdx.x;
    if (idx >= Bsz * E) return;
    int b = idx / E, e = idx % E;
    int p0 = pairs[((size_t)b * E + e) * 2 + 0];
    int p1 = pairs[((size_t)b * E + e) * 2 + 1];
    int pos = atomicAdd(&g_cursor[b * Nn + p0], 1);
    g_cols[b * E_MAX + pos] = p1;
    g_vals[b * E_MAX + pos] = g_edgew[b * E_MAX + e];
}

// ---------------- K4: X1 = featT @ gc1_w, bf16 split, register-gather ----------------
// 128 threads; tile 128 rows x 64 cols; same k-permutation as phi.
__global__ __launch_bounds__(128) void x1_mma_kernel() {
    __shared__ uint4 sW[2 * WBUF_F4];

    int tid = threadIdx.x, warp = tid >> 5, lane = tid & 31;
    int gid = lane >> 2, tig = lane & 3;
    int m0 = blockIdx.x * 128;
    int n0 = blockIdx.y * 64;

    const float4* rp[4];
    #pragma unroll
    for (int r = 0; r < 4; r++) {
        int m = m0 + warp * 32 + r * 8 + gid;
        rp[r] = (const float4*)(g_featT + (size_t)m * Cc);
    }

    uint32_t smem_base = smem_u32_of(sW);
    float4 ga[4];
    float acc[2][8][4] = {};

    {
        const uint4* src = g_gwP;                    // chunk 0, cols n0..n0+63
        #pragma unroll
        for (int i = 0; i < 2; i++) {
            int idx = tid + i * 128, pl = idx >> 6, n = idx & 63;
            cp_async16(smem_base + (uint32_t)(pl * 66 + n) * 16u,
                       src + pl * 128 + n0 + n);
        }
        CP_COMMIT();
        #pragma unroll
        for (int r = 0; r < 4; r++) ga[r] = rp[r][tig];
        CP_WAIT0();
    }
    __syncthreads();

    for (int c = 0; c < NCHUNK; c++) {
        int cur = c & 1, nxt = cur ^ 1;
        bool more = (c + 1 < NCHUNK);

        uint4 fr[4];
        #pragma unroll
        for (int r = 0; r < 4; r++) {
            float h0 = bf_round(ga[r].x), h1 = bf_round(ga[r].y);
            float h2 = bf_round(ga[r].z), h3 = bf_round(ga[r].w);
            fr[r].x = pack_bf(h0, h1);
            fr[r].y = pack_bf(h2, h3);
            fr[r].z = pack_bf(ga[r].x - h0, ga[r].y - h1);
            fr[r].w = pack_bf(ga[r].z - h2, ga[r].w - h3);
        }

        if (more) {
            const uint4* src = g_gwP + (c + 1) * 512;
            #pragma unroll
            for (int i = 0; i < 2; i++) {
                int idx = tid + i * 128, pl = idx >> 6, n = idx & 63;
                cp_async16(smem_base + (uint32_t)(nxt * WBUF_F4 + pl * 66 + n) * 16u,
                           src + pl * 128 + n0 + n);
            }
            CP_COMMIT();
            int o = (c + 1) * 4 + tig;
            #pragma unroll
            for (int r = 0; r < 4; r++) ga[r] = rp[r][o];
        }

        uint4 bfr[8];
        #pragma unroll
        for (int nt = 0; nt < 8; nt++)
            bfr[nt] = sW[cur * WBUF_F4 + tig * 66 + nt * 8 + gid];
        #pragma unroll
        for (int mt = 0; mt < 2; mt++) {
            uint32_t ah[4] = { fr[2*mt].x, fr[2*mt+1].x, fr[2*mt].y, fr[2*mt+1].y };
            uint32_t al[4] = { fr[2*mt].z, fr[2*mt+1].z, fr[2*mt].w, fr[2*mt+1].w };
            #pragma unroll
            for (int nt = 0; nt < 8; nt++) {
                uint32_t bh[2] = { bfr[nt].x, bfr[nt].y };
                uint32_t bl[2] = { bfr[nt].z, bfr[nt].w };
                mma_bf16(acc[mt][nt], ah, bh);
                mma_bf16(acc[mt][nt], ah, bl);
                mma_bf16(acc[mt][nt], al, bh);
            }
        }
        if (more) CP_WAIT0();
        __syncthreads();
    }

    #pragma unroll
    for (int mt = 0; mt < 2; mt++) {
        #pragma unroll
        for (int rh = 0; rh < 2; rh++) {
            int m = m0 + warp * 32 + mt * 16 + rh * 8 + gid;
            float* dst = g_X1 + (size_t)m * GC_HID + n0;
            #pragma unroll
            for (int nt = 0; nt < 8; nt++) {
                int col = nt * 8 + tig * 2;
                *(float2*)(dst + col) =
                    make_float2(acc[mt][nt][rh * 2 + 0], acc[mt][nt][rh * 2 + 1]);
            }
        }
    }
}

// ---------------- K5: SpMM + leaky + fused gc2 dot ----------------
__global__ __launch_bounds__(256) void spmm_kernel(const float* __restrict__ gc2, int E) {
    int warp = threadIdx.x >> 5, lane = threadIdx.x & 31;
    int n = blockIdx.x * 8 + warp;
    int b = blockIdx.y;
    int s = g_rowptr[b * (Nn + 1) + n];
    int t = g_rowptr[b * (Nn + 1) + n + 1];
    float a0 = 0, a1 = 0, a2 = 0, a3 = 0;
    const float* Xb = g_X1 + (size_t)b * Nn * GC_HID;
    for (int k = s; k < t; k++) {
        float w = g_vals[b * E_MAX + k];
        int   c = g_cols[b * E_MAX + k];
        const float* xr = Xb + (size_t)c * GC_HID + lane;
        a0 += w * xr[0];
        a1 += w * xr[32];
        a2 += w * xr[64];
        a3 += w * xr[96];
    }
    a0 = (a0 > 0.f) ? a0 : 0.2f * a0;
    a1 = (a1 > 0.f) ? a1 : 0.2f * a1;
    a2 = (a2 > 0.f) ? a2 : 0.2f * a2;
    a3 = (a3 > 0.f) ? a3 : 0.2f * a3;
    float p = a0 * gc2[lane] + a1 * gc2[lane + 32] + a2 * gc2[lane + 64] + a3 * gc2[lane + 96];
    #pragma unroll
    for (int o = 16; o; o >>= 1) p += __shfl_xor_sync(0xffffffffu, p, o);
    if (lane == 0) g_X2[b * Nn + n] = p;
}

__global__ void finalize_kernel(float* __restrict__ out, int E) {
    int idx = blockIdx.x * blockDim.x + threadIdx.x;
    if (idx >= Bsz * Nn) return;
    int b = idx / Nn, n = idx % Nn;
    int s = g_rowptr[b * (Nn + 1) + n];
    int t = g_rowptr[b * (Nn + 1) + n + 1];
    float acc = 0.f;
    for (int k = s; k < t; k++)
        acc += g_vals[b * E_MAX + k] * g_X2[b * Nn + g_cols[b * E_MAX + k]];
    out[idx] = 1.f / (1.f + expf(-acc));
}

// ---------------- launch ----------------
extern "C" void kernel_launch(void* const* d_in, const int* in_sizes, int n_in,
                              void* d_out, int out_size) {
    const float* search = (const float*)d_in[0];
    const float* xcorr  = (const float*)d_in[1];
    const int*   pairs  = (const int*)d_in[2];
    const float* phi_w1 = (const float*)d_in[3];
    const float* phi_b1 = (const float*)d_in[4];
    const float* gamma  = (const float*)d_in[5];
    const float* beta   = (const float*)d_in[6];
    const float* phi_w2 = (const float*)d_in[7];
    const float* phi_b2 = (const float*)d_in[8];
    const float* gc1_w  = (const float*)d_in[9];
    const float* gc2_w  = (const float*)d_in[10];
    float* out = (float*)d_out;

    int E = in_sizes[2] / (2 * Bsz);
    if (E > E_MAX) E = E_MAX;

    cudaFuncSetAttribute(phi_mma_kernel,
                         cudaFuncAttributeMaxDynamicSharedMemorySize, PHI_SMEM_BYTES);

    prep_kernel<<<(Bsz * Nn + 255) / 256, 256>>>(phi_w1, gc1_w);
    transpose_kernel<<<dim3(Nn / 32, Cc / 32, Bsz), dim3(32, 32)>>>(search, xcorr);
    phi_mma_kernel<<<dim3((E + BLK_E - 1) / BLK_E, Bsz), 128, PHI_SMEM_BYTES>>>(pairs, phi_b1, E);
    edge_weight_kernel<<<dim3((E + 255) / 256, Bsz), 256>>>(pairs, gamma, beta, phi_w2, phi_b2, E);
    scan_kernel<<<Bsz, 1024>>>(E);
    scatter_kernel<<<(Bsz * E + 255) / 256, 256>>>(pairs, E);
    x1_mma_kernel<<<dim3((Bsz * Nn) / 128, GC_HID / 64), 128>>>();
    spmm_kernel<<<dim3(Nn / 8, Bsz), 256>>>(gc2_w, E);
    finalize_kernel<<<(Bsz * Nn + 255) / 256, 256>>>(out, E);
}